// round 11
// baseline (speedup 1.0000x reference)
#include <cuda_runtime.h>
#include <cuda_bf16.h>
#include <cstdint>

// Problem dims (fixed)
#define Bn   64
#define Tn   512
#define Vn   256
#define En   1024
#define Hn   1024
#define Ln   2
#define H3n  3072
#define Mn   (Bn*Tn)      // 32768
#define NCTA 128

// ---------------- device scratch (static globals; no allocation) ----------------
__device__ __align__(16) float          g_gx[(size_t)Mn*H3n];       // 402 MB (reused per layer)
__device__ __align__(16) __nv_bfloat16  g_x_hi[(size_t)Mn*En];
__device__ __align__(16) __nv_bfloat16  g_x_lo[(size_t)Mn*En];
__device__ __align__(16) __nv_bfloat16  g_y1_hi[(size_t)Mn*Hn];
__device__ __align__(16) __nv_bfloat16  g_y1_lo[(size_t)Mn*Hn];
__device__ __align__(16) __nv_bfloat16  g_y2_hi[(size_t)Mn*Hn];
__device__ __align__(16) __nv_bfloat16  g_y2_lo[(size_t)Mn*Hn];
__device__ __align__(16) float          g_logits[(size_t)Mn*Vn];
__device__ __align__(16) __nv_bfloat16  g_Wih_hi[(size_t)Ln*H3n*Hn];
__device__ __align__(16) __nv_bfloat16  g_Wih_lo[(size_t)Ln*H3n*Hn];
__device__ __align__(16) __nv_bfloat16  g_Whh_hi[(size_t)Ln*H3n*Hn];
__device__ __align__(16) __nv_bfloat16  g_Whh_lo[(size_t)Ln*H3n*Hn];
__device__ __align__(16) __nv_bfloat16  g_Wout_hi[(size_t)Vn*Hn];
__device__ __align__(16) __nv_bfloat16  g_Wout_lo[(size_t)Vn*Hn];
__device__ __align__(16) __nv_bfloat16  g_h0h[(size_t)Ln*Bn*Hn];
__device__ __align__(16) __nv_bfloat16  g_h0l[(size_t)Ln*Bn*Hn];
__device__ unsigned g_flags[NCTA];     // per-CTA barrier arrival slots (epoch-valued)

// ---------------- helpers ----------------
#define MMA_BF16(d, a, b)                                                     \
  asm volatile("mma.sync.aligned.m16n8k16.row.col.f32.bf16.bf16.f32 "         \
               "{%0,%1,%2,%3},{%4,%5,%6,%7},{%8,%9},{%0,%1,%2,%3};"           \
               : "+f"(d[0]), "+f"(d[1]), "+f"(d[2]), "+f"(d[3])               \
               : "r"(a[0]), "r"(a[1]), "r"(a[2]), "r"(a[3]),                  \
                 "r"(b[0]), "r"(b[1]))

#define LDSM_X4(r0, r1, r2, r3, a)                                            \
  asm volatile("ldmatrix.sync.aligned.m8n8.x4.shared.b16 {%0,%1,%2,%3}, [%4];"\
               : "=r"(r0), "=r"(r1), "=r"(r2), "=r"(r3) : "r"(a))
#define LDSM_X2(r0, r1, a)                                                    \
  asm volatile("ldmatrix.sync.aligned.m8n8.x2.shared.b16 {%0,%1}, [%2];"      \
               : "=r"(r0), "=r"(r1) : "r"(a))

__device__ __forceinline__ unsigned lds_u32(const __nv_bfloat16* s, int row, int ld, int col) {
    return *reinterpret_cast<const unsigned*>(s + row * ld + col);
}

__device__ __forceinline__ unsigned smem_u32(const void* p) {
    return (unsigned)__cvta_generic_to_shared(p);
}

__device__ __forceinline__ void cpa16(void* dst, const void* src) {
    unsigned d = (unsigned)__cvta_generic_to_shared(dst);
    asm volatile("cp.async.cg.shared.global [%0], [%1], 16;\n" :: "r"(d), "l"(src));
}
#define CPA_COMMIT() asm volatile("cp.async.commit_group;\n" ::: "memory")
#define CPA_WAIT(n)  asm volatile("cp.async.wait_group %0;\n" :: "n"(n) : "memory")

__device__ __forceinline__ void st_release_u32(unsigned* p, unsigned v) {
    asm volatile("st.release.gpu.global.u32 [%0], %1;" :: "l"(p), "r"(v) : "memory");
}
__device__ __forceinline__ unsigned ld_acquire_u32(const unsigned* p) {
    unsigned v;
    asm volatile("ld.acquire.gpu.global.u32 %0, [%1];" : "=r"(v) : "l"(p) : "memory");
    return v;
}

// ---------------- elementwise kernels ----------------
__global__ void embed_split(const int* __restrict__ X, const float* __restrict__ emb,
                            __nv_bfloat16* __restrict__ xhi, __nv_bfloat16* __restrict__ xlo) {
    long long i = (long long)blockIdx.x * blockDim.x + threadIdx.x;
    if (i < (long long)Mn * En) {
        int m = (int)(i >> 10);
        int e = (int)(i & 1023);
        int tok = X[m];
        float v = emb[(size_t)tok * En + e];
        __nv_bfloat16 h = __float2bfloat16(v);
        xhi[i] = h;
        xlo[i] = __float2bfloat16(v - __bfloat162float(h));
    }
}

// One kernel: split W_ih, W_hh (both layers), W_out, h0 (both layers); reset barrier flags.
#define SA_T1 ((long long)Ln*H3n*Hn)                 // 6,291,456
#define SA_T2 (SA_T1 + (long long)Ln*H3n*Hn)         // 12,582,912
#define SA_T3 (SA_T2 + (long long)Vn*Hn)             // 12,845,056
#define SA_T4 (SA_T3 + (long long)Ln*Bn*Hn)          // 12,976,128
__global__ void split_all(const float* __restrict__ W_ih, const float* __restrict__ W_hh,
                          const float* __restrict__ W_out, const float* __restrict__ h0,
                          __nv_bfloat16* __restrict__ wihH, __nv_bfloat16* __restrict__ wihL,
                          __nv_bfloat16* __restrict__ whhH, __nv_bfloat16* __restrict__ whhL,
                          __nv_bfloat16* __restrict__ woH,  __nv_bfloat16* __restrict__ woL,
                          __nv_bfloat16* __restrict__ h0h,  __nv_bfloat16* __restrict__ h0l) {
    long long i = (long long)blockIdx.x * blockDim.x + threadIdx.x;
    if (i < NCTA) g_flags[(int)i] = 0u;       // reset barrier epochs (per graph replay)
    if (i >= SA_T4) return;
    float v;
    __nv_bfloat16 *ph, *pl;
    if (i < SA_T1)      { long long j = i;          v = W_ih[j];  ph = wihH + j; pl = wihL + j; }
    else if (i < SA_T2) { long long j = i - SA_T1;  v = W_hh[j];  ph = whhH + j; pl = whhL + j; }
    else if (i < SA_T3) { long long j = i - SA_T2;  v = W_out[j]; ph = woH + j;  pl = woL + j; }
    else                { long long j = i - SA_T3;  v = h0[j];    ph = h0h + j;  pl = h0l + j; }
    __nv_bfloat16 h = __float2bfloat16(v);
    *ph = h;
    *pl = __float2bfloat16(v - __bfloat162float(h));
}

__global__ void copy_out(const float* __restrict__ logits, float* __restrict__ out) {
    int i = blockIdx.x * blockDim.x + threadIdx.x;
    int b   = i / (511 * Vn);
    int rem = i - b * (511 * Vn);
    int t   = rem >> 8;
    int v   = rem & 255;
    out[i] = logits[(((size_t)b * Tn + t) << 8) + v];
}

// ---------------- big GEMM: C[M,N] = (Ahi+Alo)(Bhi+Blo)^T + bias (split-bf16) ----------------
// BM=128, BN=64, BK=32, 256 threads (8 warps 4m x 2n, warp tile 32x32).
// 3-stage cp.async pipeline, dynamic smem. (Known-good from R4.)
#define GLD 40
#define G_STAGE 15360   // elems per stage: (128+128+64+64)*40
#define SMEM_GEMM (3 * G_STAGE * 2)

__device__ __forceinline__ void gemm_load_stage(
    const __nv_bfloat16* Ahi, const __nv_bfloat16* Alo,
    const __nv_bfloat16* Bhi, const __nv_bfloat16* Blo,
    __nv_bfloat16* base, int tid, int bm, int bn, int k0, int Kdim) {
#pragma unroll
    for (int p = 0; p < 4; p++) {
        int i = tid + p * 256;
        int arr = i >> 9;
        int rem = i & 511;
        int row = rem >> 2, ch = rem & 3;
        const __nv_bfloat16* src = (arr ? Alo : Ahi) + (size_t)(bm + row) * Kdim + k0 + ch * 8;
        cpa16(base + arr * 5120 + row * GLD + ch * 8, src);
    }
#pragma unroll
    for (int p = 0; p < 2; p++) {
        int i = tid + p * 256;
        int arr = i >> 8;
        int rem = i & 255;
        int row = rem >> 2, ch = rem & 3;
        const __nv_bfloat16* src = (arr ? Blo : Bhi) + (size_t)(bn + row) * Kdim + k0 + ch * 8;
        cpa16(base + 10240 + arr * 2560 + row * GLD + ch * 8, src);
    }
    CPA_COMMIT();
}

__global__ __launch_bounds__(256, 2) void gemm_split(
    const __nv_bfloat16* __restrict__ Ahi, const __nv_bfloat16* __restrict__ Alo,
    const __nv_bfloat16* __restrict__ Bhi, const __nv_bfloat16* __restrict__ Blo,
    const float* __restrict__ bias, float* __restrict__ C,
    int Ndim, int Kdim) {
    extern __shared__ __nv_bfloat16 dsm[];

    int tid = threadIdx.x;
    int warp = tid >> 5, lane = tid & 31;
    int g = lane >> 2, tg = lane & 3;
    int wm = warp >> 1, wn = warp & 1;
    int bm = blockIdx.y * 128, bn = blockIdx.x * 64;

    float acc[2][4][4];
#pragma unroll
    for (int a = 0; a < 2; a++)
#pragma unroll
        for (int b = 0; b < 4; b++)
#pragma unroll
            for (int c = 0; c < 4; c++) acc[a][b][c] = 0.f;

    int NCk = Kdim >> 5;
    gemm_load_stage(Ahi, Alo, Bhi, Blo, dsm,           tid, bm, bn, 0,  Kdim);
    gemm_load_stage(Ahi, Alo, Bhi, Blo, dsm + G_STAGE, tid, bm, bn, 32, Kdim);

    for (int c = 0; c < NCk; c++) {
        CPA_WAIT(1);
        __syncthreads();
        if (c + 2 < NCk)
            gemm_load_stage(Ahi, Alo, Bhi, Blo, dsm + ((c + 2) % 3) * G_STAGE,
                            tid, bm, bn, (c + 2) * 32, Kdim);

        const __nv_bfloat16* sAh = dsm + (c % 3) * G_STAGE;
        const __nv_bfloat16* sAl = sAh + 5120;
        const __nv_bfloat16* sBh = sAh + 10240;
        const __nv_bfloat16* sBl = sAh + 12800;

#pragma unroll
        for (int ks = 0; ks < 2; ks++) {
            int kk = ks * 16;
            unsigned ah[2][4], al[2][4], bh[4][2], bl[4][2];
#pragma unroll
            for (int mt = 0; mt < 2; mt++) {
                int r = wm * 32 + mt * 16 + g;
                ah[mt][0] = lds_u32(sAh, r,     GLD, kk + tg * 2);
                ah[mt][1] = lds_u32(sAh, r + 8, GLD, kk + tg * 2);
                ah[mt][2] = lds_u32(sAh, r,     GLD, kk + 8 + tg * 2);
                ah[mt][3] = lds_u32(sAh, r + 8, GLD, kk + 8 + tg * 2);
                al[mt][0] = lds_u32(sAl, r,     GLD, kk + tg * 2);
                al[mt][1] = lds_u32(sAl, r + 8, GLD, kk + tg * 2);
                al[mt][2] = lds_u32(sAl, r,     GLD, kk + 8 + tg * 2);
                al[mt][3] = lds_u32(sAl, r + 8, GLD, kk + 8 + tg * 2);
            }
#pragma unroll
            for (int nt = 0; nt < 4; nt++) {
                int r = wn * 32 + nt * 8 + g;
                bh[nt][0] = lds_u32(sBh, r, GLD, kk + tg * 2);
                bh[nt][1] = lds_u32(sBh, r, GLD, kk + 8 + tg * 2);
                bl[nt][0] = lds_u32(sBl, r, GLD, kk + tg * 2);
                bl[nt][1] = lds_u32(sBl, r, GLD, kk + 8 + tg * 2);
            }
#pragma unroll
            for (int mt = 0; mt < 2; mt++)
#pragma unroll
                for (int nt = 0; nt < 4; nt++) {
                    MMA_BF16(acc[mt][nt], ah[mt], bh[nt]);
                    MMA_BF16(acc[mt][nt], ah[mt], bl[nt]);
                    MMA_BF16(acc[mt][nt], al[mt], bh[nt]);
                }
        }
    }

#pragma unroll
    for (int mt = 0; mt < 2; mt++)
#pragma unroll
        for (int nt = 0; nt < 4; nt++) {
            int r = bm + wm * 32 + mt * 16 + g;
            int cn = bn + wn * 32 + nt * 8 + tg * 2;
            float b0 = bias[cn], b1 = bias[cn + 1];
            *reinterpret_cast<float2*>(&C[(size_t)r * Ndim + cn]) =
                make_float2(acc[mt][nt][0] + b0, acc[mt][nt][1] + b1);
            *reinterpret_cast<float2*>(&C[(size_t)(r + 8) * Ndim + cn]) =
                make_float2(acc[mt][nt][2] + b0, acc[mt][nt][3] + b1);
        }
}

// ---------------- persistent GRU layer kernel ----------------
// 128 CTAs x 256 threads (8 warps). CTA owns 8 h-cols (24 W_hh rows) resident in SMEM.
// Warp (rg, kh): rg = warp>>1 owns batch rows rg*16..+16; kh = warp&1 owns K-half.
// ldmatrix fragment loads; dual accumulator chains; distributed flag grid barrier.
#define WLD 1032
#define HLD 40
#define HSTG 4
#define HWRP (HSTG * 2 * 16 * HLD)                 // 5120 bf16 per warp staging
#define SMEM_GRU (24*WLD*2*2 + 8*HWRP*2 + 64*24*4 + 24*4 + 4*32*12*4)

__device__ __forceinline__ void gru_load_h(
    const __nv_bfloat16* hinh, const __nv_bfloat16* hinl, size_t rstride,
    __nv_bfloat16* sHw, int rg, int kh, int lane, int chunk, int stage) {
#pragma unroll
    for (int p = 0; p < 4; p++) {
        int i = lane + p * 32;
        int arr = i >> 6;
        int rem = i & 63;
        int row = rem >> 2, ch = rem & 3;
        const __nv_bfloat16* src =
            (arr ? hinl : hinh) + (size_t)(rg * 16 + row) * rstride
            + kh * 512 + chunk * 32 + ch * 8;
        cpa16(sHw + (stage * 2 + arr) * 16 * HLD + row * HLD + ch * 8, src);
    }
    CPA_COMMIT();
}

__global__ void __launch_bounds__(256, 1) gru_layer(
    const __nv_bfloat16* __restrict__ Whh_hi, const __nv_bfloat16* __restrict__ Whh_lo,
    const float* __restrict__ bhh, const float* __restrict__ gx,
    const __nv_bfloat16* __restrict__ h0h, const __nv_bfloat16* __restrict__ h0l,
    const float* __restrict__ h0f,
    __nv_bfloat16* __restrict__ y_hi, __nv_bfloat16* __restrict__ y_lo,
    int epoch_base) {
    extern __shared__ char smem[];
    __nv_bfloat16* sWh = (__nv_bfloat16*)smem;                 // 24 x 1032
    __nv_bfloat16* sWl = sWh + 24 * WLD;
    __nv_bfloat16* sH  = sWl + 24 * WLD;                       // [8 warps][HSTG][hi/lo][16*40]
    float*         sGx = (float*)(sH + 8 * HWRP);              // [64][24]
    float*         sB  = sGx + 64 * 24;                        // 24
    float*         sRed= sB + 24;                              // [4 rg][32 lane][12]

    const int tid  = threadIdx.x;
    const int warp = tid >> 5;
    const int lane = tid & 31;
    const int g    = lane >> 2;
    const int tg   = lane & 3;
    const int rg   = warp >> 1;
    const int kh   = warp & 1;
    const int c0   = blockIdx.x * 8;

    // ---- load W_hh slice (hi+lo) into SMEM once ----
    for (int i = tid; i < 24 * 128; i += 256) {
        int r = i >> 7, blk = i & 127;
        int w = (r >> 3) * 1024 + c0 + (r & 7);
        *reinterpret_cast<uint4*>(sWh + r * WLD + blk * 8) =
            *(reinterpret_cast<const uint4*>(Whh_hi + (size_t)w * Hn) + blk);
        *reinterpret_cast<uint4*>(sWl + r * WLD + blk * 8) =
            *(reinterpret_cast<const uint4*>(Whh_lo + (size_t)w * Hn) + blk);
    }
    if (tid < 24) sB[tid] = bhh[(tid >> 3) * 1024 + c0 + (tid & 7)];

    // h carried in registers by kh==0 warps
    float hreg[4];
#pragma unroll
    for (int half = 0; half < 2; half++)
#pragma unroll
        for (int c = 0; c < 2; c++)
            hreg[half * 2 + c] = h0f[(rg * 16 + g + half * 8) * Hn + c0 + tg * 2 + c];

    __syncthreads();

    __nv_bfloat16* sHw = sH + warp * HWRP;
    float*         sGw = sGx + rg * 16 * 24;

    // ldmatrix lane-address constants (byte offsets)
    const unsigned sHw_u = smem_u32(sHw);
    const unsigned sWh_u = smem_u32(sWh);
    const unsigned sWl_u = smem_u32(sWl);
    const unsigned aOff  = (unsigned)(((lane & 15) * HLD + (lane >> 4) * 8) * 2);
    const unsigned b4Off = (unsigned)((((lane & 7) + ((lane >> 4) << 3)) * WLD
                                      + ((lane >> 3) & 1) * 8) * 2);
    const unsigned b2Off = (unsigned)(((16 + (lane & 7)) * WLD
                                      + ((lane >> 3) & 1) * 8) * 2);

    for (int t = 0; t < Tn; t++) {
        const __nv_bfloat16* hinh;
        const __nv_bfloat16* hinl;
        size_t rstride;
        if (t == 0) { hinh = h0h; hinl = h0l; rstride = Hn; }
        else {
            hinh = y_hi + (size_t)(t - 1) * Hn;
            hinl = y_lo + (size_t)(t - 1) * Hn;
            rstride = (size_t)Tn * Hn;
        }

        // group: gx tile (kh0 loads; kh1 commits empty group for count alignment)
        if (kh == 0) {
#pragma unroll
            for (int p = 0; p < 3; p++) {
                int i = lane + p * 32;
                int row = i / 6, seg = i % 6;
                int gate = seg >> 1, part = seg & 1;
                cpa16(sGw + row * 24 + gate * 8 + part * 4,
                      gx + ((size_t)(rg * 16 + row) * Tn + t) * H3n
                         + gate * 1024 + c0 + part * 4);
            }
        }
        CPA_COMMIT();

        // prologue: h chunks 0..2
#pragma unroll
        for (int s = 0; s < HSTG - 1; s++)
            gru_load_h(hinh, hinl, rstride, sHw, rg, kh, lane, s, s);

        float accA[3][4], accB[3][4];
#pragma unroll
        for (int a = 0; a < 3; a++)
#pragma unroll
            for (int b = 0; b < 4; b++) { accA[a][b] = 0.f; accB[a][b] = 0.f; }

        for (int kc = 0; kc < 16; kc++) {
            if (kc + 3 < 16)
                gru_load_h(hinh, hinl, rstride, sHw, rg, kh, lane, kc + 3, (kc + 3) % HSTG);

            if      (kc < 13)  CPA_WAIT(3);
            else if (kc == 13) CPA_WAIT(2);
            else if (kc == 14) CPA_WAIT(1);
            else               CPA_WAIT(0);
            __syncwarp();

            const unsigned stH = sHw_u + (unsigned)(((kc % HSTG) * 2 + 0) * 16 * HLD * 2);
            const unsigned stL = stH + 16 * HLD * 2;
#pragma unroll
            for (int ks = 0; ks < 2; ks++) {
                const unsigned kb = (unsigned)(ks * 16 * 2);
                const unsigned kcol2 = (unsigned)((kh * 512 + kc * 32 + ks * 16) * 2);
                unsigned ah[4], al[4], bh01[4], bl01[4], bh2[2], bl2[2];
                LDSM_X4(ah[0], ah[1], ah[2], ah[3], stH + aOff + kb);
                LDSM_X4(al[0], al[1], al[2], al[3], stL + aOff + kb);
                LDSM_X4(bh01[0], bh01[1], bh01[2], bh01[3], sWh_u + b4Off + kcol2);
                LDSM_X2(bh2[0], bh2[1], sWh_u + b2Off + kcol2);
                LDSM_X4(bl01[0], bl01[1], bl01[2], bl01[3], sWl_u + b4Off + kcol2);
                LDSM_X2(bl2[0], bl2[1], sWl_u + b2Off + kcol2);
                unsigned* bH[3] = {bh01, bh01 + 2, bh2};
                unsigned* bL[3] = {bl01, bl01 + 2, bl2};
#pragma unroll
                for (int nt = 0; nt < 3; nt++) {
                    MMA_BF16(accA[nt], ah, bH[nt]);   // chain A: 1 MMA per ks
                    MMA_BF16(accB[nt], ah, bL[nt]);   // chain B: 2 MMAs per ks
                    MMA_BF16(accB[nt], al, bH[nt]);
                }
            }
            __syncwarp();
        }

        float acc[3][4];
#pragma unroll
        for (int nt = 0; nt < 3; nt++)
#pragma unroll
            for (int i = 0; i < 4; i++) acc[nt][i] = accA[nt][i] + accB[nt][i];

        // ---- cross-K-half reduction: kh1 stores, kh0 adds ----
        if (kh == 1) {
            float* r = sRed + (rg * 32 + lane) * 12;
#pragma unroll
            for (int nt = 0; nt < 3; nt++)
#pragma unroll
                for (int i = 0; i < 4; i++) r[nt * 4 + i] = acc[nt][i];
        }
        __syncthreads();

        if (kh == 0) {
            const float* r = sRed + (rg * 32 + lane) * 12;
#pragma unroll
            for (int nt = 0; nt < 3; nt++)
#pragma unroll
                for (int i = 0; i < 4; i++) acc[nt][i] += r[nt * 4 + i];

            // ---- epilogue ----
#pragma unroll
            for (int half = 0; half < 2; half++) {
                __nv_bfloat16 hh2[2], hl2[2];
#pragma unroll
                for (int c = 0; c < 2; c++) {
                    int rl = g + half * 8;
                    int jl = tg * 2 + c;
                    int ai = half * 2 + c;
                    float gr = acc[0][ai] + sB[jl];
                    float gz = acc[1][ai] + sB[8 + jl];
                    float gn = acc[2][ai] + sB[16 + jl];
                    float rr = 1.f / (1.f + __expf(-(sGw[rl * 24 + jl] + gr)));
                    float zz = 1.f / (1.f + __expf(-(sGw[rl * 24 + 8 + jl] + gz)));
                    float nn = tanhf(sGw[rl * 24 + 16 + jl] + rr * gn);
                    float hv = (1.f - zz) * nn + zz * hreg[ai];
                    hreg[ai] = hv;
                    __nv_bfloat16 hh_ = __float2bfloat16(hv);
                    hh2[c] = hh_;
                    hl2[c] = __float2bfloat16(hv - __bfloat162float(hh_));
                }
                int b = rg * 16 + g + half * 8;
                size_t off = ((size_t)b * Tn + t) * Hn + c0 + tg * 2;
                *reinterpret_cast<__nv_bfloat162*>(y_hi + off) =
                    *reinterpret_cast<__nv_bfloat162*>(hh2);
                *reinterpret_cast<__nv_bfloat162*>(y_lo + off) =
                    *reinterpret_cast<__nv_bfloat162*>(hl2);
            }
        }

        // ---- distributed flag grid barrier (skip after last step) ----
        // Arrive: st.release of epoch to own slot (orders prior y stores).
        // Wait: 128 threads poll 128 per-CTA flags in parallel with ld.acquire.
        if (t < Tn - 1) {
            unsigned epoch = (unsigned)(epoch_base + t + 1);
            __syncthreads();                  // all y stores of this CTA issued
            if (tid == 0)
                st_release_u32(&g_flags[blockIdx.x], epoch);
            if (tid < NCTA) {
                while (ld_acquire_u32(&g_flags[tid]) < epoch) { }
            }
            __syncthreads();
        }
    }
}

// ---------------- host orchestration ----------------
extern "C" void kernel_launch(void* const* d_in, const int* in_sizes, int n_in,
                              void* d_out, int out_size) {
    (void)in_sizes; (void)n_in; (void)out_size;
    const int*   X     = (const int*)d_in[0];
    const float* h0    = (const float*)d_in[1];
    const float* emb   = (const float*)d_in[2];
    const float* W_ih  = (const float*)d_in[3];
    const float* W_hh  = (const float*)d_in[4];
    const float* b_ih  = (const float*)d_in[5];
    const float* b_hh  = (const float*)d_in[6];
    const float* W_out = (const float*)d_in[7];
    const float* b_out = (const float*)d_in[8];
    float* out = (float*)d_out;

    float *gx, *logits;
    __nv_bfloat16 *xhi, *xlo, *y1hi, *y1lo, *y2hi, *y2lo;
    __nv_bfloat16 *wihH, *wihL, *whhH, *whhL, *woH, *woL;
    __nv_bfloat16 *h0h, *h0lp;
    cudaGetSymbolAddress((void**)&gx, g_gx);
    cudaGetSymbolAddress((void**)&logits, g_logits);
    cudaGetSymbolAddress((void**)&xhi, g_x_hi);
    cudaGetSymbolAddress((void**)&xlo, g_x_lo);
    cudaGetSymbolAddress((void**)&y1hi, g_y1_hi);
    cudaGetSymbolAddress((void**)&y1lo, g_y1_lo);
    cudaGetSymbolAddress((void**)&y2hi, g_y2_hi);
    cudaGetSymbolAddress((void**)&y2lo, g_y2_lo);
    cudaGetSymbolAddress((void**)&wihH, g_Wih_hi);
    cudaGetSymbolAddress((void**)&wihL, g_Wih_lo);
    cudaGetSymbolAddress((void**)&whhH, g_Whh_hi);
    cudaGetSymbolAddress((void**)&whhL, g_Whh_lo);
    cudaGetSymbolAddress((void**)&woH, g_Wout_hi);
    cudaGetSymbolAddress((void**)&woL, g_Wout_lo);
    cudaGetSymbolAddress((void**)&h0h, g_h0h);
    cudaGetSymbolAddress((void**)&h0lp, g_h0l);
    const size_t HB = (size_t)Bn * Hn;

    cudaFuncSetAttribute(gru_layer, cudaFuncAttributeMaxDynamicSharedMemorySize, SMEM_GRU);
    cudaFuncSetAttribute(gemm_split, cudaFuncAttributeMaxDynamicSharedMemorySize, SMEM_GEMM);

    dim3 gg(H3n / 64, Mn / 128);

    // Launch order: embed(1), split_all(2), gemmL0(3), gruL0(4) <- ncu slot 4
    embed_split<<<(int)(((long long)Mn * En) / 256), 256>>>(X, emb, xhi, xlo);
    split_all<<<(int)((SA_T4 + 255) / 256), 256>>>(W_ih, W_hh, W_out, h0,
                                                   wihH, wihL, whhH, whhL,
                                                   woH, woL, h0h, h0lp);

    for (int l = 0; l < Ln; l++) {
        const __nv_bfloat16* aH = (l == 0) ? xhi : y1hi;
        const __nv_bfloat16* aL = (l == 0) ? xlo : y1lo;
        __nv_bfloat16* yH = (l == 0) ? y1hi : y2hi;
        __nv_bfloat16* yL = (l == 0) ? y1lo : y2lo;
        size_t wOff = (size_t)l * H3n * Hn;

        gemm_split<<<gg, 256, SMEM_GEMM>>>(aH, aL, wihH + wOff, wihL + wOff,
                                           b_ih + (size_t)l * H3n, gx, H3n, Hn);
        gru_layer<<<NCTA, 256, SMEM_GRU>>>(whhH + wOff, whhL + wOff,
                                           b_hh + (size_t)l * H3n, gx,
                                           h0h + l * HB, h0lp + l * HB,
                                           h0 + (size_t)l * HB, yH, yL,
                                           l * (Tn - 1));
    }

    dim3 gl(Vn / 64, Mn / 128);
    gemm_split<<<gl, 256, SMEM_GEMM>>>(y2hi, y2lo, woH, woL, b_out, logits, Vn, Hn);

    copy_out<<<(Bn * 511 * Vn) / 256, 256>>>(logits, out);
}

// round 12
// speedup vs baseline: 1.2238x; 1.2238x over previous
#include <cuda_runtime.h>
#include <cuda_bf16.h>
#include <cstdint>

// Problem dims (fixed)
#define Bn   64
#define Tn   512
#define Vn   256
#define En   1024
#define Hn   1024
#define Ln   2
#define H3n  3072
#define Mn   (Bn*Tn)      // 32768
#define NCTA 128

// ---------------- device scratch (static globals; no allocation) ----------------
__device__ __align__(16) float          g_gx[(size_t)Mn*H3n];       // 402 MB (reused per layer)
__device__ __align__(16) __nv_bfloat16  g_x_hi[(size_t)Mn*En];
__device__ __align__(16) __nv_bfloat16  g_x_lo[(size_t)Mn*En];
__device__ __align__(16) __nv_bfloat16  g_y1_hi[(size_t)Mn*Hn];
__device__ __align__(16) __nv_bfloat16  g_y1_lo[(size_t)Mn*Hn];
__device__ __align__(16) __nv_bfloat16  g_y2_hi[(size_t)Mn*Hn];
__device__ __align__(16) __nv_bfloat16  g_y2_lo[(size_t)Mn*Hn];
__device__ __align__(16) float          g_logits[(size_t)Mn*Vn];
__device__ __align__(16) __nv_bfloat16  g_Wih_hi[(size_t)Ln*H3n*Hn];
__device__ __align__(16) __nv_bfloat16  g_Wih_lo[(size_t)Ln*H3n*Hn];
__device__ __align__(16) __nv_bfloat16  g_Whh_hi[(size_t)Ln*H3n*Hn];
__device__ __align__(16) __nv_bfloat16  g_Whh_lo[(size_t)Ln*H3n*Hn];
__device__ __align__(16) __nv_bfloat16  g_Wout_hi[(size_t)Vn*Hn];
__device__ __align__(16) __nv_bfloat16  g_Wout_lo[(size_t)Vn*Hn];
__device__ __align__(16) __nv_bfloat16  g_h0h[(size_t)Ln*Bn*Hn];
__device__ __align__(16) __nv_bfloat16  g_h0l[(size_t)Ln*Bn*Hn];
__device__ unsigned g_barrier;

// ---------------- helpers ----------------
#define MMA_BF16(d, a, b)                                                     \
  asm volatile("mma.sync.aligned.m16n8k16.row.col.f32.bf16.bf16.f32 "         \
               "{%0,%1,%2,%3},{%4,%5,%6,%7},{%8,%9},{%0,%1,%2,%3};"           \
               : "+f"(d[0]), "+f"(d[1]), "+f"(d[2]), "+f"(d[3])               \
               : "r"(a[0]), "r"(a[1]), "r"(a[2]), "r"(a[3]),                  \
                 "r"(b[0]), "r"(b[1]))

#define LDSM_X4(r0, r1, r2, r3, a)                                            \
  asm volatile("ldmatrix.sync.aligned.m8n8.x4.shared.b16 {%0,%1,%2,%3}, [%4];"\
               : "=r"(r0), "=r"(r1), "=r"(r2), "=r"(r3) : "r"(a))
#define LDSM_X2(r0, r1, a)                                                    \
  asm volatile("ldmatrix.sync.aligned.m8n8.x2.shared.b16 {%0,%1}, [%2];"      \
               : "=r"(r0), "=r"(r1) : "r"(a))

__device__ __forceinline__ unsigned lds_u32(const __nv_bfloat16* s, int row, int ld, int col) {
    return *reinterpret_cast<const unsigned*>(s + row * ld + col);
}

__device__ __forceinline__ unsigned smem_u32(const void* p) {
    return (unsigned)__cvta_generic_to_shared(p);
}

__device__ __forceinline__ void cpa16(void* dst, const void* src) {
    unsigned d = (unsigned)__cvta_generic_to_shared(dst);
    asm volatile("cp.async.cg.shared.global [%0], [%1], 16;\n" :: "r"(d), "l"(src));
}
#define CPA_COMMIT() asm volatile("cp.async.commit_group;\n" ::: "memory")
#define CPA_WAIT(n)  asm volatile("cp.async.wait_group %0;\n" :: "n"(n) : "memory")

// ---------------- elementwise kernels ----------------
__global__ void embed_split(const int* __restrict__ X, const float* __restrict__ emb,
                            __nv_bfloat16* __restrict__ xhi, __nv_bfloat16* __restrict__ xlo) {
    long long i = (long long)blockIdx.x * blockDim.x + threadIdx.x;
    if (i < (long long)Mn * En) {
        int m = (int)(i >> 10);
        int e = (int)(i & 1023);
        int tok = X[m];
        float v = emb[(size_t)tok * En + e];
        __nv_bfloat16 h = __float2bfloat16(v);
        xhi[i] = h;
        xlo[i] = __float2bfloat16(v - __bfloat162float(h));
    }
}

// One kernel: split W_ih, W_hh (both layers), W_out, h0 (both layers); reset barrier.
#define SA_T1 ((long long)Ln*H3n*Hn)                 // 6,291,456
#define SA_T2 (SA_T1 + (long long)Ln*H3n*Hn)         // 12,582,912
#define SA_T3 (SA_T2 + (long long)Vn*Hn)             // 12,845,056
#define SA_T4 (SA_T3 + (long long)Ln*Bn*Hn)          // 12,976,128
__global__ void split_all(const float* __restrict__ W_ih, const float* __restrict__ W_hh,
                          const float* __restrict__ W_out, const float* __restrict__ h0,
                          __nv_bfloat16* __restrict__ wihH, __nv_bfloat16* __restrict__ wihL,
                          __nv_bfloat16* __restrict__ whhH, __nv_bfloat16* __restrict__ whhL,
                          __nv_bfloat16* __restrict__ woH,  __nv_bfloat16* __restrict__ woL,
                          __nv_bfloat16* __restrict__ h0h,  __nv_bfloat16* __restrict__ h0l) {
    long long i = (long long)blockIdx.x * blockDim.x + threadIdx.x;
    if (i == 0) g_barrier = 0u;
    if (i >= SA_T4) return;
    float v;
    __nv_bfloat16 *ph, *pl;
    if (i < SA_T1)      { long long j = i;          v = W_ih[j];  ph = wihH + j; pl = wihL + j; }
    else if (i < SA_T2) { long long j = i - SA_T1;  v = W_hh[j];  ph = whhH + j; pl = whhL + j; }
    else if (i < SA_T3) { long long j = i - SA_T2;  v = W_out[j]; ph = woH + j;  pl = woL + j; }
    else                { long long j = i - SA_T3;  v = h0[j];    ph = h0h + j;  pl = h0l + j; }
    __nv_bfloat16 h = __float2bfloat16(v);
    *ph = h;
    *pl = __float2bfloat16(v - __bfloat162float(h));
}

__global__ void copy_out(const float* __restrict__ logits, float* __restrict__ out) {
    int i = blockIdx.x * blockDim.x + threadIdx.x;
    int b   = i / (511 * Vn);
    int rem = i - b * (511 * Vn);
    int t   = rem >> 8;
    int v   = rem & 255;
    out[i] = logits[(((size_t)b * Tn + t) << 8) + v];
}

// ---------------- big GEMM: C[M,N] = (Ahi+Alo)(Bhi+Blo)^T + bias (split-bf16) ----------------
// BM=128, BN=64, BK=32, 256 threads (8 warps 4m x 2n, warp tile 32x32).
// 3-stage cp.async pipeline; ldmatrix fragment loads (R12: 32 LDS -> 8 LDSM per ks).
#define GLD 40
#define G_STAGE 15360   // elems per stage: (128+128+64+64)*40
#define SMEM_GEMM (3 * G_STAGE * 2)

__device__ __forceinline__ void gemm_load_stage(
    const __nv_bfloat16* Ahi, const __nv_bfloat16* Alo,
    const __nv_bfloat16* Bhi, const __nv_bfloat16* Blo,
    __nv_bfloat16* base, int tid, int bm, int bn, int k0, int Kdim) {
#pragma unroll
    for (int p = 0; p < 4; p++) {
        int i = tid + p * 256;
        int arr = i >> 9;
        int rem = i & 511;
        int row = rem >> 2, ch = rem & 3;
        const __nv_bfloat16* src = (arr ? Alo : Ahi) + (size_t)(bm + row) * Kdim + k0 + ch * 8;
        cpa16(base + arr * 5120 + row * GLD + ch * 8, src);
    }
#pragma unroll
    for (int p = 0; p < 2; p++) {
        int i = tid + p * 256;
        int arr = i >> 8;
        int rem = i & 255;
        int row = rem >> 2, ch = rem & 3;
        const __nv_bfloat16* src = (arr ? Blo : Bhi) + (size_t)(bn + row) * Kdim + k0 + ch * 8;
        cpa16(base + 10240 + arr * 2560 + row * GLD + ch * 8, src);
    }
    CPA_COMMIT();
}

__global__ __launch_bounds__(256, 2) void gemm_split(
    const __nv_bfloat16* __restrict__ Ahi, const __nv_bfloat16* __restrict__ Alo,
    const __nv_bfloat16* __restrict__ Bhi, const __nv_bfloat16* __restrict__ Blo,
    const float* __restrict__ bias, float* __restrict__ C,
    int Ndim, int Kdim) {
    extern __shared__ __nv_bfloat16 dsm[];

    int tid = threadIdx.x;
    int warp = tid >> 5, lane = tid & 31;
    int g = lane >> 2, tg = lane & 3;
    int wm = warp >> 1, wn = warp & 1;
    int bm = blockIdx.y * 128, bn = blockIdx.x * 64;

    float acc[2][4][4];
#pragma unroll
    for (int a = 0; a < 2; a++)
#pragma unroll
        for (int b = 0; b < 4; b++)
#pragma unroll
            for (int c = 0; c < 4; c++) acc[a][b][c] = 0.f;

    // ldmatrix lane-address constants (byte offsets; same mappings as gru_layer,
    // validated conflict-free for 80-byte row stride GLD=40)
    const unsigned dsm_u = smem_u32(dsm);
    const unsigned aLane = (unsigned)(((lane & 15) * GLD + (lane >> 4) * 8) * 2);
    const unsigned bLane = (unsigned)((((lane & 7) + ((lane >> 4) << 3)) * GLD
                                     + ((lane >> 3) & 1) * 8) * 2);
    const unsigned aBase = (unsigned)(wm * 32 * GLD * 2) + aLane;
    const unsigned bBase = (unsigned)(wn * 32 * GLD * 2) + bLane + 10240u * 2u;

    int NCk = Kdim >> 5;
    gemm_load_stage(Ahi, Alo, Bhi, Blo, dsm,           tid, bm, bn, 0,  Kdim);
    gemm_load_stage(Ahi, Alo, Bhi, Blo, dsm + G_STAGE, tid, bm, bn, 32, Kdim);

    for (int c = 0; c < NCk; c++) {
        CPA_WAIT(1);
        __syncthreads();
        if (c + 2 < NCk)
            gemm_load_stage(Ahi, Alo, Bhi, Blo, dsm + ((c + 2) % 3) * G_STAGE,
                            tid, bm, bn, (c + 2) * 32, Kdim);

        const unsigned st = dsm_u + (unsigned)((c % 3) * G_STAGE * 2);
        const unsigned uAh = st;                 // A hi at stage+0
        const unsigned uAl = st + 5120u * 2u;    // A lo
        const unsigned uBh = st;                 // B hi at stage+10240 (in bBase)
        const unsigned uBl = st + 2560u * 2u;    // B lo = +12800 elems total

#pragma unroll
        for (int ks = 0; ks < 2; ks++) {
            const unsigned kb = (unsigned)(ks * 16 * 2);
            unsigned ah[2][4], al[2][4], bh[4][2], bl[4][2];
#pragma unroll
            for (int mt = 0; mt < 2; mt++) {
                const unsigned mo = (unsigned)(mt * 16 * GLD * 2);
                LDSM_X4(ah[mt][0], ah[mt][1], ah[mt][2], ah[mt][3],
                        uAh + aBase + mo + kb);
                LDSM_X4(al[mt][0], al[mt][1], al[mt][2], al[mt][3],
                        uAl + aBase + mo + kb);
            }
#pragma unroll
            for (int pr = 0; pr < 2; pr++) {
                const unsigned po = (unsigned)(pr * 16 * GLD * 2);
                LDSM_X4(bh[pr * 2][0], bh[pr * 2][1], bh[pr * 2 + 1][0], bh[pr * 2 + 1][1],
                        uBh + bBase + po + kb);
                LDSM_X4(bl[pr * 2][0], bl[pr * 2][1], bl[pr * 2 + 1][0], bl[pr * 2 + 1][1],
                        uBl + bBase + po + kb);
            }
#pragma unroll
            for (int mt = 0; mt < 2; mt++)
#pragma unroll
                for (int nt = 0; nt < 4; nt++) {
                    MMA_BF16(acc[mt][nt], ah[mt], bh[nt]);
                    MMA_BF16(acc[mt][nt], ah[mt], bl[nt]);
                    MMA_BF16(acc[mt][nt], al[mt], bh[nt]);
                }
        }
    }

#pragma unroll
    for (int mt = 0; mt < 2; mt++)
#pragma unroll
        for (int nt = 0; nt < 4; nt++) {
            int r = bm + wm * 32 + mt * 16 + g;
            int cn = bn + wn * 32 + nt * 8 + tg * 2;
            float b0 = bias[cn], b1 = bias[cn + 1];
            *reinterpret_cast<float2*>(&C[(size_t)r * Ndim + cn]) =
                make_float2(acc[mt][nt][0] + b0, acc[mt][nt][1] + b1);
            *reinterpret_cast<float2*>(&C[(size_t)(r + 8) * Ndim + cn]) =
                make_float2(acc[mt][nt][2] + b0, acc[mt][nt][3] + b1);
        }
}

// ---------------- persistent GRU layer kernel (exact R10 version) ----------------
// 128 CTAs x 256 threads (8 warps). CTA owns 8 h-cols (24 W_hh rows) resident in SMEM.
// Warp (rg, kh): rg = warp>>1 owns batch rows rg*16..+16; kh = warp&1 owns K-half.
// ldmatrix fragment loads; single acc chains; atomic-counter grid barrier.
#define WLD 1032
#define HLD 40
#define HSTG 4
#define HWRP (HSTG * 2 * 16 * HLD)                 // 5120 bf16 per warp staging
#define SMEM_GRU (24*WLD*2*2 + 8*HWRP*2 + 64*24*4 + 24*4 + 4*32*12*4)

__device__ __forceinline__ void gru_load_h(
    const __nv_bfloat16* hinh, const __nv_bfloat16* hinl, size_t rstride,
    __nv_bfloat16* sHw, int rg, int kh, int lane, int chunk, int stage) {
#pragma unroll
    for (int p = 0; p < 4; p++) {
        int i = lane + p * 32;
        int arr = i >> 6;
        int rem = i & 63;
        int row = rem >> 2, ch = rem & 3;
        const __nv_bfloat16* src =
            (arr ? hinl : hinh) + (size_t)(rg * 16 + row) * rstride
            + kh * 512 + chunk * 32 + ch * 8;
        cpa16(sHw + (stage * 2 + arr) * 16 * HLD + row * HLD + ch * 8, src);
    }
    CPA_COMMIT();
}

__global__ void __launch_bounds__(256, 1) gru_layer(
    const __nv_bfloat16* __restrict__ Whh_hi, const __nv_bfloat16* __restrict__ Whh_lo,
    const float* __restrict__ bhh, const float* __restrict__ gx,
    const __nv_bfloat16* __restrict__ h0h, const __nv_bfloat16* __restrict__ h0l,
    const float* __restrict__ h0f,
    __nv_bfloat16* __restrict__ y_hi, __nv_bfloat16* __restrict__ y_lo,
    int bar_base) {
    extern __shared__ char smem[];
    __nv_bfloat16* sWh = (__nv_bfloat16*)smem;                 // 24 x 1032
    __nv_bfloat16* sWl = sWh + 24 * WLD;
    __nv_bfloat16* sH  = sWl + 24 * WLD;                       // [8 warps][HSTG][hi/lo][16*40]
    float*         sGx = (float*)(sH + 8 * HWRP);              // [64][24]
    float*         sB  = sGx + 64 * 24;                        // 24
    float*         sRed= sB + 24;                              // [4 rg][32 lane][12]

    const int tid  = threadIdx.x;
    const int warp = tid >> 5;
    const int lane = tid & 31;
    const int g    = lane >> 2;
    const int tg   = lane & 3;
    const int rg   = warp >> 1;
    const int kh   = warp & 1;
    const int c0   = blockIdx.x * 8;

    // ---- load W_hh slice (hi+lo) into SMEM once ----
    for (int i = tid; i < 24 * 128; i += 256) {
        int r = i >> 7, blk = i & 127;
        int w = (r >> 3) * 1024 + c0 + (r & 7);
        *reinterpret_cast<uint4*>(sWh + r * WLD + blk * 8) =
            *(reinterpret_cast<const uint4*>(Whh_hi + (size_t)w * Hn) + blk);
        *reinterpret_cast<uint4*>(sWl + r * WLD + blk * 8) =
            *(reinterpret_cast<const uint4*>(Whh_lo + (size_t)w * Hn) + blk);
    }
    if (tid < 24) sB[tid] = bhh[(tid >> 3) * 1024 + c0 + (tid & 7)];

    // h carried in registers by kh==0 warps
    float hreg[4];
#pragma unroll
    for (int half = 0; half < 2; half++)
#pragma unroll
        for (int c = 0; c < 2; c++)
            hreg[half * 2 + c] = h0f[(rg * 16 + g + half * 8) * Hn + c0 + tg * 2 + c];

    __syncthreads();

    __nv_bfloat16* sHw = sH + warp * HWRP;
    float*         sGw = sGx + rg * 16 * 24;

    // ldmatrix lane-address constants (byte offsets)
    const unsigned sHw_u = smem_u32(sHw);
    const unsigned sWh_u = smem_u32(sWh);
    const unsigned sWl_u = smem_u32(sWl);
    const unsigned aOff  = (unsigned)(((lane & 15) * HLD + (lane >> 4) * 8) * 2);
    const unsigned b4Off = (unsigned)((((lane & 7) + ((lane >> 4) << 3)) * WLD
                                      + ((lane >> 3) & 1) * 8) * 2);
    const unsigned b2Off = (unsigned)(((16 + (lane & 7)) * WLD
                                      + ((lane >> 3) & 1) * 8) * 2);

    for (int t = 0; t < Tn; t++) {
        const __nv_bfloat16* hinh;
        const __nv_bfloat16* hinl;
        size_t rstride;
        if (t == 0) { hinh = h0h; hinl = h0l; rstride = Hn; }
        else {
            hinh = y_hi + (size_t)(t - 1) * Hn;
            hinl = y_lo + (size_t)(t - 1) * Hn;
            rstride = (size_t)Tn * Hn;
        }

        // group: gx tile (kh0 loads; kh1 commits empty group for count alignment)
        if (kh == 0) {
#pragma unroll
            for (int p = 0; p < 3; p++) {
                int i = lane + p * 32;
                int row = i / 6, seg = i % 6;
                int gate = seg >> 1, part = seg & 1;
                cpa16(sGw + row * 24 + gate * 8 + part * 4,
                      gx + ((size_t)(rg * 16 + row) * Tn + t) * H3n
                         + gate * 1024 + c0 + part * 4);
            }
        }
        CPA_COMMIT();

        // prologue: h chunks 0..2
#pragma unroll
        for (int s = 0; s < HSTG - 1; s++)
            gru_load_h(hinh, hinl, rstride, sHw, rg, kh, lane, s, s);

        float acc[3][4];
#pragma unroll
        for (int a = 0; a < 3; a++)
#pragma unroll
            for (int b = 0; b < 4; b++) acc[a][b] = 0.f;

        for (int kc = 0; kc < 16; kc++) {
            if (kc + 3 < 16)
                gru_load_h(hinh, hinl, rstride, sHw, rg, kh, lane, kc + 3, (kc + 3) % HSTG);

            if      (kc < 13)  CPA_WAIT(3);
            else if (kc == 13) CPA_WAIT(2);
            else if (kc == 14) CPA_WAIT(1);
            else               CPA_WAIT(0);
            __syncwarp();

            const unsigned stH = sHw_u + (unsigned)(((kc % HSTG) * 2 + 0) * 16 * HLD * 2);
            const unsigned stL = stH + 16 * HLD * 2;
#pragma unroll
            for (int ks = 0; ks < 2; ks++) {
                const unsigned kb = (unsigned)(ks * 16 * 2);
                const unsigned kcol2 = (unsigned)((kh * 512 + kc * 32 + ks * 16) * 2);
                unsigned ah[4], al[4], bh01[4], bl01[4], bh2[2], bl2[2];
                LDSM_X4(ah[0], ah[1], ah[2], ah[3], stH + aOff + kb);
                LDSM_X4(al[0], al[1], al[2], al[3], stL + aOff + kb);
                LDSM_X4(bh01[0], bh01[1], bh01[2], bh01[3], sWh_u + b4Off + kcol2);
                LDSM_X2(bh2[0], bh2[1], sWh_u + b2Off + kcol2);
                LDSM_X4(bl01[0], bl01[1], bl01[2], bl01[3], sWl_u + b4Off + kcol2);
                LDSM_X2(bl2[0], bl2[1], sWl_u + b2Off + kcol2);
                unsigned* bH[3] = {bh01, bh01 + 2, bh2};
                unsigned* bL[3] = {bl01, bl01 + 2, bl2};
#pragma unroll
                for (int nt = 0; nt < 3; nt++) {
                    MMA_BF16(acc[nt], ah, bH[nt]);
                    MMA_BF16(acc[nt], ah, bL[nt]);
                    MMA_BF16(acc[nt], al, bH[nt]);
                }
            }
            __syncwarp();
        }

        // ---- cross-K-half reduction: kh1 stores, kh0 adds ----
        if (kh == 1) {
            float* r = sRed + (rg * 32 + lane) * 12;
#pragma unroll
            for (int nt = 0; nt < 3; nt++)
#pragma unroll
                for (int i = 0; i < 4; i++) r[nt * 4 + i] = acc[nt][i];
        }
        __syncthreads();

        if (kh == 0) {
            const float* r = sRed + (rg * 32 + lane) * 12;
#pragma unroll
            for (int nt = 0; nt < 3; nt++)
#pragma unroll
                for (int i = 0; i < 4; i++) acc[nt][i] += r[nt * 4 + i];

            // ---- epilogue ----
#pragma unroll
            for (int half = 0; half < 2; half++) {
                __nv_bfloat16 hh2[2], hl2[2];
#pragma unroll
                for (int c = 0; c < 2; c++) {
                    int rl = g + half * 8;
                    int jl = tg * 2 + c;
                    int ai = half * 2 + c;
                    float gr = acc[0][ai] + sB[jl];
                    float gz = acc[1][ai] + sB[8 + jl];
                    float gn = acc[2][ai] + sB[16 + jl];
                    float rr = 1.f / (1.f + __expf(-(sGw[rl * 24 + jl] + gr)));
                    float zz = 1.f / (1.f + __expf(-(sGw[rl * 24 + 8 + jl] + gz)));
                    float nn = tanhf(sGw[rl * 24 + 16 + jl] + rr * gn);
                    float hv = (1.f - zz) * nn + zz * hreg[ai];
                    hreg[ai] = hv;
                    __nv_bfloat16 hh_ = __float2bfloat16(hv);
                    hh2[c] = hh_;
                    hl2[c] = __float2bfloat16(hv - __bfloat162float(hh_));
                }
                int b = rg * 16 + g + half * 8;
                size_t off = ((size_t)b * Tn + t) * Hn + c0 + tg * 2;
                *reinterpret_cast<__nv_bfloat162*>(y_hi + off) =
                    *reinterpret_cast<__nv_bfloat162*>(hh2);
                *reinterpret_cast<__nv_bfloat162*>(y_lo + off) =
                    *reinterpret_cast<__nv_bfloat162*>(hl2);
            }
        }

        // ---- grid barrier (R6/R10-style; skip after last step) ----
        if (t < Tn - 1) {
            __syncthreads();
            if (tid == 0) {
                __threadfence();
                atomicAdd(&g_barrier, 1u);
                unsigned tgt = (unsigned)(bar_base + (t + 1) * NCTA);
                while (*(volatile unsigned*)&g_barrier < tgt) { }
                __threadfence();
            }
            __syncthreads();
        }
    }
}

// ---------------- host orchestration ----------------
extern "C" void kernel_launch(void* const* d_in, const int* in_sizes, int n_in,
                              void* d_out, int out_size) {
    (void)in_sizes; (void)n_in; (void)out_size;
    const int*   X     = (const int*)d_in[0];
    const float* h0    = (const float*)d_in[1];
    const float* emb   = (const float*)d_in[2];
    const float* W_ih  = (const float*)d_in[3];
    const float* W_hh  = (const float*)d_in[4];
    const float* b_ih  = (const float*)d_in[5];
    const float* b_hh  = (const float*)d_in[6];
    const float* W_out = (const float*)d_in[7];
    const float* b_out = (const float*)d_in[8];
    float* out = (float*)d_out;

    float *gx, *logits;
    __nv_bfloat16 *xhi, *xlo, *y1hi, *y1lo, *y2hi, *y2lo;
    __nv_bfloat16 *wihH, *wihL, *whhH, *whhL, *woH, *woL;
    __nv_bfloat16 *h0h, *h0lp;
    cudaGetSymbolAddress((void**)&gx, g_gx);
    cudaGetSymbolAddress((void**)&logits, g_logits);
    cudaGetSymbolAddress((void**)&xhi, g_x_hi);
    cudaGetSymbolAddress((void**)&xlo, g_x_lo);
    cudaGetSymbolAddress((void**)&y1hi, g_y1_hi);
    cudaGetSymbolAddress((void**)&y1lo, g_y1_lo);
    cudaGetSymbolAddress((void**)&y2hi, g_y2_hi);
    cudaGetSymbolAddress((void**)&y2lo, g_y2_lo);
    cudaGetSymbolAddress((void**)&wihH, g_Wih_hi);
    cudaGetSymbolAddress((void**)&wihL, g_Wih_lo);
    cudaGetSymbolAddress((void**)&whhH, g_Whh_hi);
    cudaGetSymbolAddress((void**)&whhL, g_Whh_lo);
    cudaGetSymbolAddress((void**)&woH, g_Wout_hi);
    cudaGetSymbolAddress((void**)&woL, g_Wout_lo);
    cudaGetSymbolAddress((void**)&h0h, g_h0h);
    cudaGetSymbolAddress((void**)&h0lp, g_h0l);
    const size_t HB = (size_t)Bn * Hn;

    cudaFuncSetAttribute(gru_layer, cudaFuncAttributeMaxDynamicSharedMemorySize, SMEM_GRU);
    cudaFuncSetAttribute(gemm_split, cudaFuncAttributeMaxDynamicSharedMemorySize, SMEM_GEMM);

    dim3 gg(H3n / 64, Mn / 128);

    // Launch order identical to R10: embed(1), split_all(2), gemmL0(3), gruL0(4)
    embed_split<<<(int)(((long long)Mn * En) / 256), 256>>>(X, emb, xhi, xlo);
    split_all<<<(int)((SA_T4 + 255) / 256), 256>>>(W_ih, W_hh, W_out, h0,
                                                   wihH, wihL, whhH, whhL,
                                                   woH, woL, h0h, h0lp);

    for (int l = 0; l < Ln; l++) {
        const __nv_bfloat16* aH = (l == 0) ? xhi : y1hi;
        const __nv_bfloat16* aL = (l == 0) ? xlo : y1lo;
        __nv_bfloat16* yH = (l == 0) ? y1hi : y2hi;
        __nv_bfloat16* yL = (l == 0) ? y1lo : y2lo;
        size_t wOff = (size_t)l * H3n * Hn;

        gemm_split<<<gg, 256, SMEM_GEMM>>>(aH, aL, wihH + wOff, wihL + wOff,
                                           b_ih + (size_t)l * H3n, gx, H3n, Hn);
        gru_layer<<<NCTA, 256, SMEM_GRU>>>(whhH + wOff, whhL + wOff,
                                           b_hh + (size_t)l * H3n, gx,
                                           h0h + l * HB, h0lp + l * HB,
                                           h0 + (size_t)l * HB, yH, yL,
                                           l * (Tn - 1) * NCTA);
    }

    dim3 gl(Vn / 64, Mn / 128);
    gemm_split<<<gl, 256, SMEM_GEMM>>>(y2hi, y2lo, woH, woL, b_out, logits, Vn, Hn);

    copy_out<<<(Bn * 511 * Vn) / 256, 256>>>(logits, out);
}

// round 13
// speedup vs baseline: 1.2319x; 1.0067x over previous
#include <cuda_runtime.h>
#include <cuda_bf16.h>
#include <cstdint>

// Problem dims (fixed)
#define Bn   64
#define Tn   512
#define Vn   256
#define En   1024
#define Hn   1024
#define Ln   2
#define H3n  3072
#define Mn   (Bn*Tn)      // 32768
#define NCTA 128

// ---------------- device scratch (static globals; no allocation) ----------------
__device__ __align__(16) float          g_gx[(size_t)Mn*H3n];       // 402 MB (reused per layer)
__device__ __align__(16) __nv_bfloat16  g_x_hi[(size_t)Mn*En];
__device__ __align__(16) __nv_bfloat16  g_x_lo[(size_t)Mn*En];
__device__ __align__(16) __nv_bfloat16  g_y1_hi[(size_t)Mn*Hn];
__device__ __align__(16) __nv_bfloat16  g_y1_lo[(size_t)Mn*Hn];
__device__ __align__(16) __nv_bfloat16  g_y2_hi[(size_t)Mn*Hn];
__device__ __align__(16) __nv_bfloat16  g_y2_lo[(size_t)Mn*Hn];
__device__ __align__(16) float          g_logits[(size_t)Mn*Vn];
__device__ __align__(16) __nv_bfloat16  g_Wih_hi[(size_t)Ln*H3n*Hn];
__device__ __align__(16) __nv_bfloat16  g_Wih_lo[(size_t)Ln*H3n*Hn];
__device__ __align__(16) __nv_bfloat16  g_Whh_hi[(size_t)Ln*H3n*Hn];
__device__ __align__(16) __nv_bfloat16  g_Whh_lo[(size_t)Ln*H3n*Hn];
__device__ __align__(16) __nv_bfloat16  g_Wout_hi[(size_t)Vn*Hn];
__device__ __align__(16) __nv_bfloat16  g_Wout_lo[(size_t)Vn*Hn];
__device__ __align__(16) __nv_bfloat16  g_h0h[(size_t)Ln*Bn*Hn];
__device__ __align__(16) __nv_bfloat16  g_h0l[(size_t)Ln*Bn*Hn];
__device__ unsigned g_barrier;

// ---------------- helpers ----------------
#define MMA_BF16(d, a, b)                                                     \
  asm volatile("mma.sync.aligned.m16n8k16.row.col.f32.bf16.bf16.f32 "         \
               "{%0,%1,%2,%3},{%4,%5,%6,%7},{%8,%9},{%0,%1,%2,%3};"           \
               : "+f"(d[0]), "+f"(d[1]), "+f"(d[2]), "+f"(d[3])               \
               : "r"(a[0]), "r"(a[1]), "r"(a[2]), "r"(a[3]),                  \
                 "r"(b[0]), "r"(b[1]))

#define LDSM_X4(r0, r1, r2, r3, a)                                            \
  asm volatile("ldmatrix.sync.aligned.m8n8.x4.shared.b16 {%0,%1,%2,%3}, [%4];"\
               : "=r"(r0), "=r"(r1), "=r"(r2), "=r"(r3) : "r"(a))
#define LDSM_X2(r0, r1, a)                                                    \
  asm volatile("ldmatrix.sync.aligned.m8n8.x2.shared.b16 {%0,%1}, [%2];"      \
               : "=r"(r0), "=r"(r1) : "r"(a))

__device__ __forceinline__ unsigned lds_u32(const __nv_bfloat16* s, int row, int ld, int col) {
    return *reinterpret_cast<const unsigned*>(s + row * ld + col);
}

__device__ __forceinline__ unsigned smem_u32(const void* p) {
    return (unsigned)__cvta_generic_to_shared(p);
}

__device__ __forceinline__ void cpa16(void* dst, const void* src) {
    unsigned d = (unsigned)__cvta_generic_to_shared(dst);
    asm volatile("cp.async.cg.shared.global [%0], [%1], 16;\n" :: "r"(d), "l"(src));
}
#define CPA_COMMIT() asm volatile("cp.async.commit_group;\n" ::: "memory")
#define CPA_WAIT(n)  asm volatile("cp.async.wait_group %0;\n" :: "n"(n) : "memory")

// ---------------- elementwise kernels ----------------
__global__ void embed_split(const int* __restrict__ X, const float* __restrict__ emb,
                            __nv_bfloat16* __restrict__ xhi, __nv_bfloat16* __restrict__ xlo) {
    long long i = (long long)blockIdx.x * blockDim.x + threadIdx.x;
    if (i < (long long)Mn * En) {
        int m = (int)(i >> 10);
        int e = (int)(i & 1023);
        int tok = X[m];
        float v = emb[(size_t)tok * En + e];
        __nv_bfloat16 h = __float2bfloat16(v);
        xhi[i] = h;
        xlo[i] = __float2bfloat16(v - __bfloat162float(h));
    }
}

// One kernel: split W_ih, W_hh (both layers), W_out, h0 (both layers); reset barrier.
#define SA_T1 ((long long)Ln*H3n*Hn)                 // 6,291,456
#define SA_T2 (SA_T1 + (long long)Ln*H3n*Hn)         // 12,582,912
#define SA_T3 (SA_T2 + (long long)Vn*Hn)             // 12,845,056
#define SA_T4 (SA_T3 + (long long)Ln*Bn*Hn)          // 12,976,128
__global__ void split_all(const float* __restrict__ W_ih, const float* __restrict__ W_hh,
                          const float* __restrict__ W_out, const float* __restrict__ h0,
                          __nv_bfloat16* __restrict__ wihH, __nv_bfloat16* __restrict__ wihL,
                          __nv_bfloat16* __restrict__ whhH, __nv_bfloat16* __restrict__ whhL,
                          __nv_bfloat16* __restrict__ woH,  __nv_bfloat16* __restrict__ woL,
                          __nv_bfloat16* __restrict__ h0h,  __nv_bfloat16* __restrict__ h0l) {
    long long i = (long long)blockIdx.x * blockDim.x + threadIdx.x;
    if (i == 0) g_barrier = 0u;
    if (i >= SA_T4) return;
    float v;
    __nv_bfloat16 *ph, *pl;
    if (i < SA_T1)      { long long j = i;          v = W_ih[j];  ph = wihH + j; pl = wihL + j; }
    else if (i < SA_T2) { long long j = i - SA_T1;  v = W_hh[j];  ph = whhH + j; pl = whhL + j; }
    else if (i < SA_T3) { long long j = i - SA_T2;  v = W_out[j]; ph = woH + j;  pl = woL + j; }
    else                { long long j = i - SA_T3;  v = h0[j];    ph = h0h + j;  pl = h0l + j; }
    __nv_bfloat16 h = __float2bfloat16(v);
    *ph = h;
    *pl = __float2bfloat16(v - __bfloat162float(h));
}

__global__ void copy_out(const float* __restrict__ logits, float* __restrict__ out) {
    int i = blockIdx.x * blockDim.x + threadIdx.x;
    int b   = i / (511 * Vn);
    int rem = i - b * (511 * Vn);
    int t   = rem >> 8;
    int v   = rem & 255;
    out[i] = logits[(((size_t)b * Tn + t) << 8) + v];
}

// ---------------- big GEMM: C[M,N] = (Ahi+Alo)(Bhi+Blo)^T + bias (split-bf16) ----------------
// R13: BM=128, BN=128, BK=32, 512 threads (16 warps 4m x 4n, warp tile 32x32).
// 3-stage cp.async pipeline; scalar LDS fragment loads (R10-proven inner code).
#define GLD 40
#define G_STAGE 20480   // elems per stage: (128+128+128+128)*40
#define SMEM_GEMM (3 * G_STAGE * 2)

__device__ __forceinline__ void gemm_load_stage(
    const __nv_bfloat16* Ahi, const __nv_bfloat16* Alo,
    const __nv_bfloat16* Bhi, const __nv_bfloat16* Blo,
    __nv_bfloat16* base, int tid, int bm, int bn, int k0, int Kdim) {
#pragma unroll
    for (int p = 0; p < 2; p++) {       // A hi+lo: 1024 cpa16 ops
        int i = tid + p * 512;
        int arr = i >> 9;
        int rem = i & 511;
        int row = rem >> 2, ch = rem & 3;
        const __nv_bfloat16* src = (arr ? Alo : Ahi) + (size_t)(bm + row) * Kdim + k0 + ch * 8;
        cpa16(base + arr * 5120 + row * GLD + ch * 8, src);
    }
#pragma unroll
    for (int p = 0; p < 2; p++) {       // B hi+lo: 1024 cpa16 ops
        int i = tid + p * 512;
        int arr = i >> 9;
        int rem = i & 511;
        int row = rem >> 2, ch = rem & 3;
        const __nv_bfloat16* src = (arr ? Blo : Bhi) + (size_t)(bn + row) * Kdim + k0 + ch * 8;
        cpa16(base + 10240 + arr * 5120 + row * GLD + ch * 8, src);
    }
    CPA_COMMIT();
}

__global__ __launch_bounds__(512, 1) void gemm_split(
    const __nv_bfloat16* __restrict__ Ahi, const __nv_bfloat16* __restrict__ Alo,
    const __nv_bfloat16* __restrict__ Bhi, const __nv_bfloat16* __restrict__ Blo,
    const float* __restrict__ bias, float* __restrict__ C,
    int Ndim, int Kdim) {
    extern __shared__ __nv_bfloat16 dsm[];

    int tid = threadIdx.x;
    int warp = tid >> 5, lane = tid & 31;
    int g = lane >> 2, tg = lane & 3;
    int wm = warp >> 2, wn = warp & 3;
    int bm = blockIdx.y * 128, bn = blockIdx.x * 128;

    float acc[2][4][4];
#pragma unroll
    for (int a = 0; a < 2; a++)
#pragma unroll
        for (int b = 0; b < 4; b++)
#pragma unroll
            for (int c = 0; c < 4; c++) acc[a][b][c] = 0.f;

    int NCk = Kdim >> 5;
    gemm_load_stage(Ahi, Alo, Bhi, Blo, dsm,           tid, bm, bn, 0,  Kdim);
    gemm_load_stage(Ahi, Alo, Bhi, Blo, dsm + G_STAGE, tid, bm, bn, 32, Kdim);

    for (int c = 0; c < NCk; c++) {
        CPA_WAIT(1);
        __syncthreads();
        if (c + 2 < NCk)
            gemm_load_stage(Ahi, Alo, Bhi, Blo, dsm + ((c + 2) % 3) * G_STAGE,
                            tid, bm, bn, (c + 2) * 32, Kdim);

        const __nv_bfloat16* sAh = dsm + (c % 3) * G_STAGE;
        const __nv_bfloat16* sAl = sAh + 5120;
        const __nv_bfloat16* sBh = sAh + 10240;
        const __nv_bfloat16* sBl = sAh + 15360;

#pragma unroll
        for (int ks = 0; ks < 2; ks++) {
            int kk = ks * 16;
            unsigned ah[2][4], al[2][4], bh[4][2], bl[4][2];
#pragma unroll
            for (int mt = 0; mt < 2; mt++) {
                int r = wm * 32 + mt * 16 + g;
                ah[mt][0] = lds_u32(sAh, r,     GLD, kk + tg * 2);
                ah[mt][1] = lds_u32(sAh, r + 8, GLD, kk + tg * 2);
                ah[mt][2] = lds_u32(sAh, r,     GLD, kk + 8 + tg * 2);
                ah[mt][3] = lds_u32(sAh, r + 8, GLD, kk + 8 + tg * 2);
                al[mt][0] = lds_u32(sAl, r,     GLD, kk + tg * 2);
                al[mt][1] = lds_u32(sAl, r + 8, GLD, kk + tg * 2);
                al[mt][2] = lds_u32(sAl, r,     GLD, kk + 8 + tg * 2);
                al[mt][3] = lds_u32(sAl, r + 8, GLD, kk + 8 + tg * 2);
            }
#pragma unroll
            for (int nt = 0; nt < 4; nt++) {
                int r = wn * 32 + nt * 8 + g;
                bh[nt][0] = lds_u32(sBh, r, GLD, kk + tg * 2);
                bh[nt][1] = lds_u32(sBh, r, GLD, kk + 8 + tg * 2);
                bl[nt][0] = lds_u32(sBl, r, GLD, kk + tg * 2);
                bl[nt][1] = lds_u32(sBl, r, GLD, kk + 8 + tg * 2);
            }
#pragma unroll
            for (int mt = 0; mt < 2; mt++)
#pragma unroll
                for (int nt = 0; nt < 4; nt++) {
                    MMA_BF16(acc[mt][nt], ah[mt], bh[nt]);
                    MMA_BF16(acc[mt][nt], ah[mt], bl[nt]);
                    MMA_BF16(acc[mt][nt], al[mt], bh[nt]);
                }
        }
    }

#pragma unroll
    for (int mt = 0; mt < 2; mt++)
#pragma unroll
        for (int nt = 0; nt < 4; nt++) {
            int r = bm + wm * 32 + mt * 16 + g;
            int cn = bn + wn * 32 + nt * 8 + tg * 2;
            float b0 = bias[cn], b1 = bias[cn + 1];
            *reinterpret_cast<float2*>(&C[(size_t)r * Ndim + cn]) =
                make_float2(acc[mt][nt][0] + b0, acc[mt][nt][1] + b1);
            *reinterpret_cast<float2*>(&C[(size_t)(r + 8) * Ndim + cn]) =
                make_float2(acc[mt][nt][2] + b0, acc[mt][nt][3] + b1);
        }
}

// ---------------- persistent GRU layer kernel (exact R10 version) ----------------
// 128 CTAs x 256 threads (8 warps). CTA owns 8 h-cols (24 W_hh rows) resident in SMEM.
// Warp (rg, kh): rg = warp>>1 owns batch rows rg*16..+16; kh = warp&1 owns K-half.
// ldmatrix fragment loads; single acc chains; atomic-counter grid barrier.
#define WLD 1032
#define HLD 40
#define HSTG 4
#define HWRP (HSTG * 2 * 16 * HLD)                 // 5120 bf16 per warp staging
#define SMEM_GRU (24*WLD*2*2 + 8*HWRP*2 + 64*24*4 + 24*4 + 4*32*12*4)

__device__ __forceinline__ void gru_load_h(
    const __nv_bfloat16* hinh, const __nv_bfloat16* hinl, size_t rstride,
    __nv_bfloat16* sHw, int rg, int kh, int lane, int chunk, int stage) {
#pragma unroll
    for (int p = 0; p < 4; p++) {
        int i = lane + p * 32;
        int arr = i >> 6;
        int rem = i & 63;
        int row = rem >> 2, ch = rem & 3;
        const __nv_bfloat16* src =
            (arr ? hinl : hinh) + (size_t)(rg * 16 + row) * rstride
            + kh * 512 + chunk * 32 + ch * 8;
        cpa16(sHw + (stage * 2 + arr) * 16 * HLD + row * HLD + ch * 8, src);
    }
    CPA_COMMIT();
}

__global__ void __launch_bounds__(256, 1) gru_layer(
    const __nv_bfloat16* __restrict__ Whh_hi, const __nv_bfloat16* __restrict__ Whh_lo,
    const float* __restrict__ bhh, const float* __restrict__ gx,
    const __nv_bfloat16* __restrict__ h0h, const __nv_bfloat16* __restrict__ h0l,
    const float* __restrict__ h0f,
    __nv_bfloat16* __restrict__ y_hi, __nv_bfloat16* __restrict__ y_lo,
    int bar_base) {
    extern __shared__ char smem[];
    __nv_bfloat16* sWh = (__nv_bfloat16*)smem;                 // 24 x 1032
    __nv_bfloat16* sWl = sWh + 24 * WLD;
    __nv_bfloat16* sH  = sWl + 24 * WLD;                       // [8 warps][HSTG][hi/lo][16*40]
    float*         sGx = (float*)(sH + 8 * HWRP);              // [64][24]
    float*         sB  = sGx + 64 * 24;                        // 24
    float*         sRed= sB + 24;                              // [4 rg][32 lane][12]

    const int tid  = threadIdx.x;
    const int warp = tid >> 5;
    const int lane = tid & 31;
    const int g    = lane >> 2;
    const int tg   = lane & 3;
    const int rg   = warp >> 1;
    const int kh   = warp & 1;
    const int c0   = blockIdx.x * 8;

    // ---- load W_hh slice (hi+lo) into SMEM once ----
    for (int i = tid; i < 24 * 128; i += 256) {
        int r = i >> 7, blk = i & 127;
        int w = (r >> 3) * 1024 + c0 + (r & 7);
        *reinterpret_cast<uint4*>(sWh + r * WLD + blk * 8) =
            *(reinterpret_cast<const uint4*>(Whh_hi + (size_t)w * Hn) + blk);
        *reinterpret_cast<uint4*>(sWl + r * WLD + blk * 8) =
            *(reinterpret_cast<const uint4*>(Whh_lo + (size_t)w * Hn) + blk);
    }
    if (tid < 24) sB[tid] = bhh[(tid >> 3) * 1024 + c0 + (tid & 7)];

    // h carried in registers by kh==0 warps
    float hreg[4];
#pragma unroll
    for (int half = 0; half < 2; half++)
#pragma unroll
        for (int c = 0; c < 2; c++)
            hreg[half * 2 + c] = h0f[(rg * 16 + g + half * 8) * Hn + c0 + tg * 2 + c];

    __syncthreads();

    __nv_bfloat16* sHw = sH + warp * HWRP;
    float*         sGw = sGx + rg * 16 * 24;

    // ldmatrix lane-address constants (byte offsets)
    const unsigned sHw_u = smem_u32(sHw);
    const unsigned sWh_u = smem_u32(sWh);
    const unsigned sWl_u = smem_u32(sWl);
    const unsigned aOff  = (unsigned)(((lane & 15) * HLD + (lane >> 4) * 8) * 2);
    const unsigned b4Off = (unsigned)((((lane & 7) + ((lane >> 4) << 3)) * WLD
                                      + ((lane >> 3) & 1) * 8) * 2);
    const unsigned b2Off = (unsigned)(((16 + (lane & 7)) * WLD
                                      + ((lane >> 3) & 1) * 8) * 2);

    for (int t = 0; t < Tn; t++) {
        const __nv_bfloat16* hinh;
        const __nv_bfloat16* hinl;
        size_t rstride;
        if (t == 0) { hinh = h0h; hinl = h0l; rstride = Hn; }
        else {
            hinh = y_hi + (size_t)(t - 1) * Hn;
            hinl = y_lo + (size_t)(t - 1) * Hn;
            rstride = (size_t)Tn * Hn;
        }

        // group: gx tile (kh0 loads; kh1 commits empty group for count alignment)
        if (kh == 0) {
#pragma unroll
            for (int p = 0; p < 3; p++) {
                int i = lane + p * 32;
                int row = i / 6, seg = i % 6;
                int gate = seg >> 1, part = seg & 1;
                cpa16(sGw + row * 24 + gate * 8 + part * 4,
                      gx + ((size_t)(rg * 16 + row) * Tn + t) * H3n
                         + gate * 1024 + c0 + part * 4);
            }
        }
        CPA_COMMIT();

        // prologue: h chunks 0..2
#pragma unroll
        for (int s = 0; s < HSTG - 1; s++)
            gru_load_h(hinh, hinl, rstride, sHw, rg, kh, lane, s, s);

        float acc[3][4];
#pragma unroll
        for (int a = 0; a < 3; a++)
#pragma unroll
            for (int b = 0; b < 4; b++) acc[a][b] = 0.f;

        for (int kc = 0; kc < 16; kc++) {
            if (kc + 3 < 16)
                gru_load_h(hinh, hinl, rstride, sHw, rg, kh, lane, kc + 3, (kc + 3) % HSTG);

            if      (kc < 13)  CPA_WAIT(3);
            else if (kc == 13) CPA_WAIT(2);
            else if (kc == 14) CPA_WAIT(1);
            else               CPA_WAIT(0);
            __syncwarp();

            const unsigned stH = sHw_u + (unsigned)(((kc % HSTG) * 2 + 0) * 16 * HLD * 2);
            const unsigned stL = stH + 16 * HLD * 2;
#pragma unroll
            for (int ks = 0; ks < 2; ks++) {
                const unsigned kb = (unsigned)(ks * 16 * 2);
                const unsigned kcol2 = (unsigned)((kh * 512 + kc * 32 + ks * 16) * 2);
                unsigned ah[4], al[4], bh01[4], bl01[4], bh2[2], bl2[2];
                LDSM_X4(ah[0], ah[1], ah[2], ah[3], stH + aOff + kb);
                LDSM_X4(al[0], al[1], al[2], al[3], stL + aOff + kb);
                LDSM_X4(bh01[0], bh01[1], bh01[2], bh01[3], sWh_u + b4Off + kcol2);
                LDSM_X2(bh2[0], bh2[1], sWh_u + b2Off + kcol2);
                LDSM_X4(bl01[0], bl01[1], bl01[2], bl01[3], sWl_u + b4Off + kcol2);
                LDSM_X2(bl2[0], bl2[1], sWl_u + b2Off + kcol2);
                unsigned* bH[3] = {bh01, bh01 + 2, bh2};
                unsigned* bL[3] = {bl01, bl01 + 2, bl2};
#pragma unroll
                for (int nt = 0; nt < 3; nt++) {
                    MMA_BF16(acc[nt], ah, bH[nt]);
                    MMA_BF16(acc[nt], ah, bL[nt]);
                    MMA_BF16(acc[nt], al, bH[nt]);
                }
            }
            __syncwarp();
        }

        // ---- cross-K-half reduction: kh1 stores, kh0 adds ----
        if (kh == 1) {
            float* r = sRed + (rg * 32 + lane) * 12;
#pragma unroll
            for (int nt = 0; nt < 3; nt++)
#pragma unroll
                for (int i = 0; i < 4; i++) r[nt * 4 + i] = acc[nt][i];
        }
        __syncthreads();

        if (kh == 0) {
            const float* r = sRed + (rg * 32 + lane) * 12;
#pragma unroll
            for (int nt = 0; nt < 3; nt++)
#pragma unroll
                for (int i = 0; i < 4; i++) acc[nt][i] += r[nt * 4 + i];

            // ---- epilogue ----
#pragma unroll
            for (int half = 0; half < 2; half++) {
                __nv_bfloat16 hh2[2], hl2[2];
#pragma unroll
                for (int c = 0; c < 2; c++) {
                    int rl = g + half * 8;
                    int jl = tg * 2 + c;
                    int ai = half * 2 + c;
                    float gr = acc[0][ai] + sB[jl];
                    float gz = acc[1][ai] + sB[8 + jl];
                    float gn = acc[2][ai] + sB[16 + jl];
                    float rr = 1.f / (1.f + __expf(-(sGw[rl * 24 + jl] + gr)));
                    float zz = 1.f / (1.f + __expf(-(sGw[rl * 24 + 8 + jl] + gz)));
                    float nn = tanhf(sGw[rl * 24 + 16 + jl] + rr * gn);
                    float hv = (1.f - zz) * nn + zz * hreg[ai];
                    hreg[ai] = hv;
                    __nv_bfloat16 hh_ = __float2bfloat16(hv);
                    hh2[c] = hh_;
                    hl2[c] = __float2bfloat16(hv - __bfloat162float(hh_));
                }
                int b = rg * 16 + g + half * 8;
                size_t off = ((size_t)b * Tn + t) * Hn + c0 + tg * 2;
                *reinterpret_cast<__nv_bfloat162*>(y_hi + off) =
                    *reinterpret_cast<__nv_bfloat162*>(hh2);
                *reinterpret_cast<__nv_bfloat162*>(y_lo + off) =
                    *reinterpret_cast<__nv_bfloat162*>(hl2);
            }
        }

        // ---- grid barrier (R6/R10-style; skip after last step) ----
        if (t < Tn - 1) {
            __syncthreads();
            if (tid == 0) {
                __threadfence();
                atomicAdd(&g_barrier, 1u);
                unsigned tgt = (unsigned)(bar_base + (t + 1) * NCTA);
                while (*(volatile unsigned*)&g_barrier < tgt) { }
                __threadfence();
            }
            __syncthreads();
        }
    }
}

// ---------------- host orchestration ----------------
extern "C" void kernel_launch(void* const* d_in, const int* in_sizes, int n_in,
                              void* d_out, int out_size) {
    (void)in_sizes; (void)n_in; (void)out_size;
    const int*   X     = (const int*)d_in[0];
    const float* h0    = (const float*)d_in[1];
    const float* emb   = (const float*)d_in[2];
    const float* W_ih  = (const float*)d_in[3];
    const float* W_hh  = (const float*)d_in[4];
    const float* b_ih  = (const float*)d_in[5];
    const float* b_hh  = (const float*)d_in[6];
    const float* W_out = (const float*)d_in[7];
    const float* b_out = (const float*)d_in[8];
    float* out = (float*)d_out;

    float *gx, *logits;
    __nv_bfloat16 *xhi, *xlo, *y1hi, *y1lo, *y2hi, *y2lo;
    __nv_bfloat16 *wihH, *wihL, *whhH, *whhL, *woH, *woL;
    __nv_bfloat16 *h0h, *h0lp;
    cudaGetSymbolAddress((void**)&gx, g_gx);
    cudaGetSymbolAddress((void**)&logits, g_logits);
    cudaGetSymbolAddress((void**)&xhi, g_x_hi);
    cudaGetSymbolAddress((void**)&xlo, g_x_lo);
    cudaGetSymbolAddress((void**)&y1hi, g_y1_hi);
    cudaGetSymbolAddress((void**)&y1lo, g_y1_lo);
    cudaGetSymbolAddress((void**)&y2hi, g_y2_hi);
    cudaGetSymbolAddress((void**)&y2lo, g_y2_lo);
    cudaGetSymbolAddress((void**)&wihH, g_Wih_hi);
    cudaGetSymbolAddress((void**)&wihL, g_Wih_lo);
    cudaGetSymbolAddress((void**)&whhH, g_Whh_hi);
    cudaGetSymbolAddress((void**)&whhL, g_Whh_lo);
    cudaGetSymbolAddress((void**)&woH, g_Wout_hi);
    cudaGetSymbolAddress((void**)&woL, g_Wout_lo);
    cudaGetSymbolAddress((void**)&h0h, g_h0h);
    cudaGetSymbolAddress((void**)&h0lp, g_h0l);
    const size_t HB = (size_t)Bn * Hn;

    cudaFuncSetAttribute(gru_layer, cudaFuncAttributeMaxDynamicSharedMemorySize, SMEM_GRU);
    cudaFuncSetAttribute(gemm_split, cudaFuncAttributeMaxDynamicSharedMemorySize, SMEM_GEMM);

    dim3 gg(H3n / 128, Mn / 128);

    // Launch order identical to R10: embed(1), split_all(2), gemmL0(3), gruL0(4)
    embed_split<<<(int)(((long long)Mn * En) / 256), 256>>>(X, emb, xhi, xlo);
    split_all<<<(int)((SA_T4 + 255) / 256), 256>>>(W_ih, W_hh, W_out, h0,
                                                   wihH, wihL, whhH, whhL,
                                                   woH, woL, h0h, h0lp);

    for (int l = 0; l < Ln; l++) {
        const __nv_bfloat16* aH = (l == 0) ? xhi : y1hi;
        const __nv_bfloat16* aL = (l == 0) ? xlo : y1lo;
        __nv_bfloat16* yH = (l == 0) ? y1hi : y2hi;
        __nv_bfloat16* yL = (l == 0) ? y1lo : y2lo;
        size_t wOff = (size_t)l * H3n * Hn;

        gemm_split<<<gg, 512, SMEM_GEMM>>>(aH, aL, wihH + wOff, wihL + wOff,
                                           b_ih + (size_t)l * H3n, gx, H3n, Hn);
        gru_layer<<<NCTA, 256, SMEM_GRU>>>(whhH + wOff, whhL + wOff,
                                           b_hh + (size_t)l * H3n, gx,
                                           h0h + l * HB, h0lp + l * HB,
                                           h0 + (size_t)l * HB, yH, yL,
                                           l * (Tn - 1) * NCTA);
    }

    dim3 gl(Vn / 128, Mn / 128);
    gemm_split<<<gl, 512, SMEM_GEMM>>>(y2hi, y2lo, woH, woL, b_out, logits, Vn, Hn);

    copy_out<<<(Bn * 511 * Vn) / 256, 256>>>(logits, out);
}

// round 14
// speedup vs baseline: 1.5929x; 1.2930x over previous
#include <cuda_runtime.h>
#include <cuda_fp16.h>
#include <cstdint>

// Problem dims (fixed)
#define Bn   64
#define Tn   512
#define Vn   256
#define En   1024
#define Hn   1024
#define Ln   2
#define H3n  3072
#define Mn   (Bn*Tn)      // 32768
#define NCTA 128
#define LOSCALE 512.0f
#define LOINV   (1.0f/512.0f)

// ---------------- device scratch (static globals; no allocation) ----------------
__device__ __align__(16) float   g_gx[(size_t)Mn*H3n];
__device__ __align__(16) __half  g_x_hi[(size_t)Mn*En];
__device__ __align__(16) __half  g_y1_hi[(size_t)Mn*Hn];
__device__ __align__(16) __half  g_y1_lo[(size_t)Mn*Hn];      // scaled x512 (unused by L2 input GEMM)
__device__ __align__(16) __half  g_y2_hi[(size_t)Mn*Hn];
__device__ __align__(16) __half  g_y2_lo[(size_t)Mn*Hn];      // scaled x512 (output GEMM term)
__device__ __align__(16) float   g_logits[(size_t)Mn*Vn];
__device__ __align__(16) __half  g_Wih_hi[(size_t)Ln*H3n*Hn];
__device__ __align__(16) __half  g_Wih_lo[(size_t)Ln*H3n*Hn]; // scaled x512
__device__ __align__(16) __half  g_Whh_hi[(size_t)Ln*H3n*Hn];
__device__ __align__(16) __half  g_Whh_lo[(size_t)Ln*H3n*Hn]; // scaled x512
__device__ __align__(16) __half  g_Wout_hi[(size_t)Vn*Hn];
__device__ __align__(16) __half  g_Wout_lo[(size_t)Vn*Hn];    // scaled x512
__device__ __align__(16) __half  g_h0h[(size_t)Ln*Bn*Hn];
__device__ __align__(16) __half  g_h0l[(size_t)Ln*Bn*Hn];     // unused by MMA (kept for split_all simplicity)
__device__ unsigned g_barrier;

// ---------------- helpers ----------------
#define MMA_F16(d, a, b)                                                      \
  asm volatile("mma.sync.aligned.m16n8k16.row.col.f32.f16.f16.f32 "           \
               "{%0,%1,%2,%3},{%4,%5,%6,%7},{%8,%9},{%0,%1,%2,%3};"           \
               : "+f"(d[0]), "+f"(d[1]), "+f"(d[2]), "+f"(d[3])               \
               : "r"(a[0]), "r"(a[1]), "r"(a[2]), "r"(a[3]),                  \
                 "r"(b[0]), "r"(b[1]))

#define LDSM_X4(r0, r1, r2, r3, a)                                            \
  asm volatile("ldmatrix.sync.aligned.m8n8.x4.shared.b16 {%0,%1,%2,%3}, [%4];"\
               : "=r"(r0), "=r"(r1), "=r"(r2), "=r"(r3) : "r"(a))
#define LDSM_X2(r0, r1, a)                                                    \
  asm volatile("ldmatrix.sync.aligned.m8n8.x2.shared.b16 {%0,%1}, [%2];"      \
               : "=r"(r0), "=r"(r1) : "r"(a))

__device__ __forceinline__ unsigned lds_u32(const __half* s, int row, int ld, int col) {
    return *reinterpret_cast<const unsigned*>(s + row * ld + col);
}

__device__ __forceinline__ unsigned smem_u32(const void* p) {
    return (unsigned)__cvta_generic_to_shared(p);
}

__device__ __forceinline__ void cpa16(void* dst, const void* src) {
    unsigned d = (unsigned)__cvta_generic_to_shared(dst);
    asm volatile("cp.async.cg.shared.global [%0], [%1], 16;\n" :: "r"(d), "l"(src));
}
#define CPA_COMMIT() asm volatile("cp.async.commit_group;\n" ::: "memory")
#define CPA_WAIT(n)  asm volatile("cp.async.wait_group %0;\n" :: "n"(n) : "memory")

// ---------------- elementwise kernels ----------------
__global__ void embed_split(const int* __restrict__ X, const float* __restrict__ emb,
                            __half* __restrict__ xhi) {
    long long i = (long long)blockIdx.x * blockDim.x + threadIdx.x;
    if (i < (long long)Mn * En) {
        int m = (int)(i >> 10);
        int e = (int)(i & 1023);
        int tok = X[m];
        xhi[i] = __float2half(emb[(size_t)tok * En + e]);
    }
}

// One kernel: split W_ih, W_hh (both layers), W_out, h0 (both layers); reset barrier.
// lo components stored pre-scaled by 512 (keeps them in fp16 normal range).
#define SA_T1 ((long long)Ln*H3n*Hn)                 // 6,291,456
#define SA_T2 (SA_T1 + (long long)Ln*H3n*Hn)         // 12,582,912
#define SA_T3 (SA_T2 + (long long)Vn*Hn)             // 12,845,056
#define SA_T4 (SA_T3 + (long long)Ln*Bn*Hn)          // 12,976,128
__global__ void split_all(const float* __restrict__ W_ih, const float* __restrict__ W_hh,
                          const float* __restrict__ W_out, const float* __restrict__ h0,
                          __half* __restrict__ wihH, __half* __restrict__ wihL,
                          __half* __restrict__ whhH, __half* __restrict__ whhL,
                          __half* __restrict__ woH,  __half* __restrict__ woL,
                          __half* __restrict__ h0h,  __half* __restrict__ h0l) {
    long long i = (long long)blockIdx.x * blockDim.x + threadIdx.x;
    if (i == 0) g_barrier = 0u;
    if (i >= SA_T4) return;
    float v;
    __half *ph, *pl;
    if (i < SA_T1)      { long long j = i;          v = W_ih[j];  ph = wihH + j; pl = wihL + j; }
    else if (i < SA_T2) { long long j = i - SA_T1;  v = W_hh[j];  ph = whhH + j; pl = whhL + j; }
    else if (i < SA_T3) { long long j = i - SA_T2;  v = W_out[j]; ph = woH + j;  pl = woL + j; }
    else                { long long j = i - SA_T3;  v = h0[j];    ph = h0h + j;  pl = h0l + j; }
    __half h = __float2half(v);
    *ph = h;
    *pl = __float2half((v - __half2float(h)) * LOSCALE);
}

__global__ void copy_out(const float* __restrict__ logits, float* __restrict__ out) {
    int i = blockIdx.x * blockDim.x + threadIdx.x;
    int b   = i / (511 * Vn);
    int rem = i - b * (511 * Vn);
    int t   = rem >> 8;
    int v   = rem & 255;
    out[i] = logits[(((size_t)b * Tn + t) << 8) + v];
}

// ---------------- big GEMM (split-fp16) ----------------
// C = A_hi*(Bh + Bl/512) [+ A_lo/512 * Bh when TERMS==3] + bias
// BM=128, BN=64, BK=32, 256 threads (8 warps 4m x 2n, warp tile 32x32). 3-stage cp.async.
#define GLD 40
#define G_STAGE 15360   // elems: Ah[0,5120) Al[5120,10240) Bh[10240,12800) Bl[12800,15360)
#define SMEM_GEMM (3 * G_STAGE * 2)

template <int TERMS>
__device__ __forceinline__ void gemm_load_stage(
    const __half* Ahi, const __half* Alo,
    const __half* Bhi, const __half* Blo,
    __half* base, int tid, int bm, int bn, int k0, int Kdim) {
#pragma unroll
    for (int p = 0; p < 2; p++) {                    // A hi: 512 ops
        int i = tid + p * 256;
        int row = i >> 2, ch = i & 3;
        cpa16(base + row * GLD + ch * 8,
              Ahi + (size_t)(bm + row) * Kdim + k0 + ch * 8);
    }
    if (TERMS == 3) {
#pragma unroll
        for (int p = 0; p < 2; p++) {                // A lo: 512 ops
            int i = tid + p * 256;
            int row = i >> 2, ch = i & 3;
            cpa16(base + 5120 + row * GLD + ch * 8,
                  Alo + (size_t)(bm + row) * Kdim + k0 + ch * 8);
        }
    }
    {                                                // B hi: 256 ops
        int row = tid >> 2, ch = tid & 3;
        cpa16(base + 10240 + row * GLD + ch * 8,
              Bhi + (size_t)(bn + row) * Kdim + k0 + ch * 8);
        cpa16(base + 12800 + row * GLD + ch * 8,     // B lo: 256 ops
              Blo + (size_t)(bn + row) * Kdim + k0 + ch * 8);
    }
    CPA_COMMIT();
}

template <int TERMS>
__global__ __launch_bounds__(256) void gemm_split(
    const __half* __restrict__ Ahi, const __half* __restrict__ Alo,
    const __half* __restrict__ Bhi, const __half* __restrict__ Blo,
    const float* __restrict__ bias, float* __restrict__ C,
    int Ndim, int Kdim) {
    extern __shared__ __half dsm[];

    int tid = threadIdx.x;
    int warp = tid >> 5, lane = tid & 31;
    int g = lane >> 2, tg = lane & 3;
    int wm = warp >> 1, wn = warp & 1;
    int bm = blockIdx.y * 128, bn = blockIdx.x * 64;

    float acc[2][4][4];
#pragma unroll
    for (int a = 0; a < 2; a++)
#pragma unroll
        for (int b = 0; b < 4; b++)
#pragma unroll
            for (int c = 0; c < 4; c++) acc[a][b][c] = 0.f;

    int NCk = Kdim >> 5;
    gemm_load_stage<TERMS>(Ahi, Alo, Bhi, Blo, dsm,           tid, bm, bn, 0,  Kdim);
    gemm_load_stage<TERMS>(Ahi, Alo, Bhi, Blo, dsm + G_STAGE, tid, bm, bn, 32, Kdim);

    for (int c = 0; c < NCk; c++) {
        CPA_WAIT(1);
        __syncthreads();
        if (c + 2 < NCk)
            gemm_load_stage<TERMS>(Ahi, Alo, Bhi, Blo, dsm + ((c + 2) % 3) * G_STAGE,
                                   tid, bm, bn, (c + 2) * 32, Kdim);

        const __half* sAh = dsm + (c % 3) * G_STAGE;
        const __half* sAl = sAh + 5120;
        const __half* sBh = sAh + 10240;
        const __half* sBl = sAh + 12800;

#pragma unroll
        for (int ks = 0; ks < 2; ks++) {
            int kk = ks * 16;
            unsigned ah[2][4], al[2][4], bh[4][2], bl[4][2];
#pragma unroll
            for (int mt = 0; mt < 2; mt++) {
                int r = wm * 32 + mt * 16 + g;
                ah[mt][0] = lds_u32(sAh, r,     GLD, kk + tg * 2);
                ah[mt][1] = lds_u32(sAh, r + 8, GLD, kk + tg * 2);
                ah[mt][2] = lds_u32(sAh, r,     GLD, kk + 8 + tg * 2);
                ah[mt][3] = lds_u32(sAh, r + 8, GLD, kk + 8 + tg * 2);
                if (TERMS == 3) {
                    al[mt][0] = lds_u32(sAl, r,     GLD, kk + tg * 2);
                    al[mt][1] = lds_u32(sAl, r + 8, GLD, kk + tg * 2);
                    al[mt][2] = lds_u32(sAl, r,     GLD, kk + 8 + tg * 2);
                    al[mt][3] = lds_u32(sAl, r + 8, GLD, kk + 8 + tg * 2);
                }
            }
#pragma unroll
            for (int nt = 0; nt < 4; nt++) {
                int r = wn * 32 + nt * 8 + g;
                bh[nt][0] = lds_u32(sBh, r, GLD, kk + tg * 2);
                bh[nt][1] = lds_u32(sBh, r, GLD, kk + 8 + tg * 2);
                bl[nt][0] = lds_u32(sBl, r, GLD, kk + tg * 2);
                bl[nt][1] = lds_u32(sBl, r, GLD, kk + 8 + tg * 2);
            }
#pragma unroll
            for (int mt = 0; mt < 2; mt++)
#pragma unroll
                for (int nt = 0; nt < 4; nt++) {
                    // lo-term in a short-lived temp, folded with exact 1/512
                    float tmp[4] = {0.f, 0.f, 0.f, 0.f};
                    MMA_F16(tmp, ah[mt], bl[nt]);
                    if (TERMS == 3) MMA_F16(tmp, al[mt], bh[nt]);
                    MMA_F16(acc[mt][nt], ah[mt], bh[nt]);
#pragma unroll
                    for (int q = 0; q < 4; q++) acc[mt][nt][q] += tmp[q] * LOINV;
                }
        }
    }

#pragma unroll
    for (int mt = 0; mt < 2; mt++)
#pragma unroll
        for (int nt = 0; nt < 4; nt++) {
            int r = bm + wm * 32 + mt * 16 + g;
            int cn = bn + wn * 32 + nt * 8 + tg * 2;
            float b0 = bias[cn], b1 = bias[cn + 1];
            *reinterpret_cast<float2*>(&C[(size_t)r * Ndim + cn]) =
                make_float2(acc[mt][nt][0] + b0, acc[mt][nt][1] + b1);
            *reinterpret_cast<float2*>(&C[(size_t)(r + 8) * Ndim + cn]) =
                make_float2(acc[mt][nt][2] + b0, acc[mt][nt][3] + b1);
        }
}

// ---------------- persistent GRU layer kernel (2-term fp16) ----------------
// 128 CTAs x 256 threads (8 warps). CTA owns 8 h-cols (24 W rows, hi+lo in SMEM).
// Warp (rg, kh): rg = warp>>1 owns batch rows rg*16..+16; kh = warp&1 owns K-half.
// h is single fp16; W split with lo x512; acc + accLo/512.
#define WLD 1032
#define HLD 40
#define HSTG 4
#define HWRP (HSTG * 16 * HLD)                       // 2560 fp16 per warp staging
#define SMEM_GRU (24*WLD*2*2 + 8*HWRP*2 + 64*24*4 + 24*4 + 4*32*12*4)

__device__ __forceinline__ void gru_load_h(
    const __half* hin, size_t rstride,
    __half* sHw, int rg, int kh, int lane, int chunk, int stage) {
#pragma unroll
    for (int p = 0; p < 2; p++) {
        int i = lane + p * 32;
        int row = i >> 2, ch = i & 3;
        cpa16(sHw + stage * 16 * HLD + row * HLD + ch * 8,
              hin + (size_t)(rg * 16 + row) * rstride + kh * 512 + chunk * 32 + ch * 8);
    }
    CPA_COMMIT();
}

__global__ void __launch_bounds__(256, 1) gru_layer(
    const __half* __restrict__ Whh_hi, const __half* __restrict__ Whh_lo,
    const float* __restrict__ bhh, const float* __restrict__ gx,
    const __half* __restrict__ h0h,
    const float* __restrict__ h0f,
    __half* __restrict__ y_hi, __half* __restrict__ y_lo,
    int bar_base) {
    extern __shared__ char smem[];
    __half* sWh = (__half*)smem;                     // 24 x 1032
    __half* sWl = sWh + 24 * WLD;
    __half* sH  = sWl + 24 * WLD;                    // [8 warps][HSTG][16*40]
    float*  sGx = (float*)(sH + 8 * HWRP);           // [64][24]
    float*  sB  = sGx + 64 * 24;                     // 24
    float*  sRed= sB + 24;                           // [4 rg][32 lane][12]

    const int tid  = threadIdx.x;
    const int warp = tid >> 5;
    const int lane = tid & 31;
    const int g    = lane >> 2;
    const int tg   = lane & 3;
    const int rg   = warp >> 1;
    const int kh   = warp & 1;
    const int c0   = blockIdx.x * 8;

    // ---- load W_hh slice (hi+lo) into SMEM once ----
    for (int i = tid; i < 24 * 128; i += 256) {
        int r = i >> 7, blk = i & 127;
        int w = (r >> 3) * 1024 + c0 + (r & 7);
        *reinterpret_cast<uint4*>(sWh + r * WLD + blk * 8) =
            *(reinterpret_cast<const uint4*>(Whh_hi + (size_t)w * Hn) + blk);
        *reinterpret_cast<uint4*>(sWl + r * WLD + blk * 8) =
            *(reinterpret_cast<const uint4*>(Whh_lo + (size_t)w * Hn) + blk);
    }
    if (tid < 24) sB[tid] = bhh[(tid >> 3) * 1024 + c0 + (tid & 7)];

    // h carried in registers by kh==0 warps
    float hreg[4];
#pragma unroll
    for (int half = 0; half < 2; half++)
#pragma unroll
        for (int c = 0; c < 2; c++)
            hreg[half * 2 + c] = h0f[(rg * 16 + g + half * 8) * Hn + c0 + tg * 2 + c];

    __syncthreads();

    __half* sHw = sH + warp * HWRP;
    float*  sGw = sGx + rg * 16 * 24;

    // ldmatrix lane-address constants (byte offsets)
    const unsigned sHw_u = smem_u32(sHw);
    const unsigned sWh_u = smem_u32(sWh);
    const unsigned sWl_u = smem_u32(sWl);
    const unsigned aOff  = (unsigned)(((lane & 15) * HLD + (lane >> 4) * 8) * 2);
    const unsigned b4Off = (unsigned)((((lane & 7) + ((lane >> 4) << 3)) * WLD
                                      + ((lane >> 3) & 1) * 8) * 2);
    const unsigned b2Off = (unsigned)(((16 + (lane & 7)) * WLD
                                      + ((lane >> 3) & 1) * 8) * 2);

    for (int t = 0; t < Tn; t++) {
        const __half* hin;
        size_t rstride;
        if (t == 0) { hin = h0h; rstride = Hn; }
        else        { hin = y_hi + (size_t)(t - 1) * Hn; rstride = (size_t)Tn * Hn; }

        // group: gx tile (kh0 loads; kh1 commits empty group for count alignment)
        if (kh == 0) {
#pragma unroll
            for (int p = 0; p < 3; p++) {
                int i = lane + p * 32;
                int row = i / 6, seg = i % 6;
                int gate = seg >> 1, part = seg & 1;
                cpa16(sGw + row * 24 + gate * 8 + part * 4,
                      gx + ((size_t)(rg * 16 + row) * Tn + t) * H3n
                         + gate * 1024 + c0 + part * 4);
            }
        }
        CPA_COMMIT();

        // prologue: h chunks 0..2
#pragma unroll
        for (int s = 0; s < HSTG - 1; s++)
            gru_load_h(hin, rstride, sHw, rg, kh, lane, s, s);

        float acc[3][4], accLo[3][4];
#pragma unroll
        for (int a = 0; a < 3; a++)
#pragma unroll
            for (int b = 0; b < 4; b++) { acc[a][b] = 0.f; accLo[a][b] = 0.f; }

        for (int kc = 0; kc < 16; kc++) {
            if (kc + 3 < 16)
                gru_load_h(hin, rstride, sHw, rg, kh, lane, kc + 3, (kc + 3) % HSTG);

            if      (kc < 13)  CPA_WAIT(3);
            else if (kc == 13) CPA_WAIT(2);
            else if (kc == 14) CPA_WAIT(1);
            else               CPA_WAIT(0);
            __syncwarp();

            const unsigned stH = sHw_u + (unsigned)((kc % HSTG) * 16 * HLD * 2);
#pragma unroll
            for (int ks = 0; ks < 2; ks++) {
                const unsigned kb = (unsigned)(ks * 16 * 2);
                const unsigned kcol2 = (unsigned)((kh * 512 + kc * 32 + ks * 16) * 2);
                unsigned ah[4], bh01[4], bl01[4], bh2[2], bl2[2];
                LDSM_X4(ah[0], ah[1], ah[2], ah[3], stH + aOff + kb);
                LDSM_X4(bh01[0], bh01[1], bh01[2], bh01[3], sWh_u + b4Off + kcol2);
                LDSM_X2(bh2[0], bh2[1], sWh_u + b2Off + kcol2);
                LDSM_X4(bl01[0], bl01[1], bl01[2], bl01[3], sWl_u + b4Off + kcol2);
                LDSM_X2(bl2[0], bl2[1], sWl_u + b2Off + kcol2);
                unsigned* bH[3] = {bh01, bh01 + 2, bh2};
                unsigned* bL[3] = {bl01, bl01 + 2, bl2};
#pragma unroll
                for (int nt = 0; nt < 3; nt++) {
                    MMA_F16(acc[nt], ah, bH[nt]);
                    MMA_F16(accLo[nt], ah, bL[nt]);
                }
            }
            __syncwarp();
        }

        // fold scaled lo term (exact /512)
#pragma unroll
        for (int nt = 0; nt < 3; nt++)
#pragma unroll
            for (int i = 0; i < 4; i++) acc[nt][i] += accLo[nt][i] * LOINV;

        // ---- cross-K-half reduction: kh1 stores, kh0 adds ----
        if (kh == 1) {
            float* r = sRed + (rg * 32 + lane) * 12;
#pragma unroll
            for (int nt = 0; nt < 3; nt++)
#pragma unroll
                for (int i = 0; i < 4; i++) r[nt * 4 + i] = acc[nt][i];
        }
        __syncthreads();

        if (kh == 0) {
            const float* r = sRed + (rg * 32 + lane) * 12;
#pragma unroll
            for (int nt = 0; nt < 3; nt++)
#pragma unroll
                for (int i = 0; i < 4; i++) acc[nt][i] += r[nt * 4 + i];

            // ---- epilogue ----
#pragma unroll
            for (int half = 0; half < 2; half++) {
                __half hh2[2], hl2[2];
#pragma unroll
                for (int c = 0; c < 2; c++) {
                    int rl = g + half * 8;
                    int jl = tg * 2 + c;
                    int ai = half * 2 + c;
                    float gr = acc[0][ai] + sB[jl];
                    float gz = acc[1][ai] + sB[8 + jl];
                    float gn = acc[2][ai] + sB[16 + jl];
                    float rr = 1.f / (1.f + __expf(-(sGw[rl * 24 + jl] + gr)));
                    float zz = 1.f / (1.f + __expf(-(sGw[rl * 24 + 8 + jl] + gz)));
                    float nn = tanhf(sGw[rl * 24 + 16 + jl] + rr * gn);
                    float hv = (1.f - zz) * nn + zz * hreg[ai];
                    hreg[ai] = hv;
                    __half h_ = __float2half(hv);
                    hh2[c] = h_;
                    hl2[c] = __float2half((hv - __half2float(h_)) * LOSCALE);
                }
                int b = rg * 16 + g + half * 8;
                size_t off = ((size_t)b * Tn + t) * Hn + c0 + tg * 2;
                *reinterpret_cast<__half2*>(y_hi + off) = *reinterpret_cast<__half2*>(hh2);
                *reinterpret_cast<__half2*>(y_lo + off) = *reinterpret_cast<__half2*>(hl2);
            }
        }

        // ---- grid barrier (R10-style; skip after last step) ----
        if (t < Tn - 1) {
            __syncthreads();
            if (tid == 0) {
                __threadfence();
                atomicAdd(&g_barrier, 1u);
                unsigned tgt = (unsigned)(bar_base + (t + 1) * NCTA);
                while (*(volatile unsigned*)&g_barrier < tgt) { }
                __threadfence();
            }
            __syncthreads();
        }
    }
}

// ---------------- host orchestration ----------------
extern "C" void kernel_launch(void* const* d_in, const int* in_sizes, int n_in,
                              void* d_out, int out_size) {
    (void)in_sizes; (void)n_in; (void)out_size;
    const int*   X     = (const int*)d_in[0];
    const float* h0    = (const float*)d_in[1];
    const float* emb   = (const float*)d_in[2];
    const float* W_ih  = (const float*)d_in[3];
    const float* W_hh  = (const float*)d_in[4];
    const float* b_ih  = (const float*)d_in[5];
    const float* b_hh  = (const float*)d_in[6];
    const float* W_out = (const float*)d_in[7];
    const float* b_out = (const float*)d_in[8];
    float* out = (float*)d_out;

    float *gx, *logits;
    __half *xhi, *y1hi, *y1lo, *y2hi, *y2lo;
    __half *wihH, *wihL, *whhH, *whhL, *woH, *woL;
    __half *h0h, *h0lp;
    cudaGetSymbolAddress((void**)&gx, g_gx);
    cudaGetSymbolAddress((void**)&logits, g_logits);
    cudaGetSymbolAddress((void**)&xhi, g_x_hi);
    cudaGetSymbolAddress((void**)&y1hi, g_y1_hi);
    cudaGetSymbolAddress((void**)&y1lo, g_y1_lo);
    cudaGetSymbolAddress((void**)&y2hi, g_y2_hi);
    cudaGetSymbolAddress((void**)&y2lo, g_y2_lo);
    cudaGetSymbolAddress((void**)&wihH, g_Wih_hi);
    cudaGetSymbolAddress((void**)&wihL, g_Wih_lo);
    cudaGetSymbolAddress((void**)&whhH, g_Whh_hi);
    cudaGetSymbolAddress((void**)&whhL, g_Whh_lo);
    cudaGetSymbolAddress((void**)&woH, g_Wout_hi);
    cudaGetSymbolAddress((void**)&woL, g_Wout_lo);
    cudaGetSymbolAddress((void**)&h0h, g_h0h);
    cudaGetSymbolAddress((void**)&h0lp, g_h0l);
    const size_t HB = (size_t)Bn * Hn;

    cudaFuncSetAttribute(gru_layer, cudaFuncAttributeMaxDynamicSharedMemorySize, SMEM_GRU);
    cudaFuncSetAttribute(gemm_split<2>, cudaFuncAttributeMaxDynamicSharedMemorySize, SMEM_GEMM);
    cudaFuncSetAttribute(gemm_split<3>, cudaFuncAttributeMaxDynamicSharedMemorySize, SMEM_GEMM);

    dim3 gg(H3n / 64, Mn / 128);

    // Launch order: embed(1), split_all(2), gemmL0(3), gruL0(4) <- ncu slot 4
    embed_split<<<(int)(((long long)Mn * En) / 256), 256>>>(X, emb, xhi);
    split_all<<<(int)((SA_T4 + 255) / 256), 256>>>(W_ih, W_hh, W_out, h0,
                                                   wihH, wihL, whhH, whhL,
                                                   woH, woL, h0h, h0lp);

    for (int l = 0; l < Ln; l++) {
        const __half* aH = (l == 0) ? xhi : y1hi;
        __half* yH = (l == 0) ? y1hi : y2hi;
        __half* yL = (l == 0) ? y1lo : y2lo;
        size_t wOff = (size_t)l * H3n * Hn;

        // input GEMM: 2-term (A plain fp16, W split)
        gemm_split<2><<<gg, 256, SMEM_GEMM>>>(aH, aH, wihH + wOff, wihL + wOff,
                                              b_ih + (size_t)l * H3n, gx, H3n, Hn);
        gru_layer<<<NCTA, 256, SMEM_GRU>>>(whhH + wOff, whhL + wOff,
                                           b_hh + (size_t)l * H3n, gx,
                                           h0h + l * HB,
                                           h0 + (size_t)l * HB, yH, yL,
                                           l * (Tn - 1) * NCTA);
    }

    // output GEMM: 3-term (y split + W split; both lo x512, single fold)
    dim3 gl(Vn / 64, Mn / 128);
    gemm_split<3><<<gl, 256, SMEM_GEMM>>>(y2hi, y2lo, woH, woL, b_out, logits, Vn, Hn);

    copy_out<<<(Bn * 511 * Vn) / 256, 256>>>(logits, out);
}

// round 15
// speedup vs baseline: 1.9235x; 1.2076x over previous
#include <cuda_runtime.h>
#include <cuda_fp16.h>
#include <cstdint>

// Problem dims (fixed)
#define Bn   64
#define Tn   512
#define Vn   256
#define En   1024
#define Hn   1024
#define Ln   2
#define H3n  3072
#define Mn   (Bn*Tn)      // 32768
#define NCTA 128
#define LOSCALE 512.0f
#define LOINV   (1.0f/512.0f)

// ---------------- device scratch (static globals; no allocation) ----------------
__device__ __align__(16) float   g_gx[(size_t)Mn*H3n];
__device__ __align__(16) __half  g_x_hi[(size_t)Mn*En];
__device__ __align__(16) __half  g_y1_hi[(size_t)Mn*Hn];
__device__ __align__(16) __half  g_y1_lo[(size_t)Mn*Hn];      // scaled x512
__device__ __align__(16) __half  g_y2_hi[(size_t)Mn*Hn];
__device__ __align__(16) __half  g_y2_lo[(size_t)Mn*Hn];      // scaled x512 (output GEMM term)
__device__ __align__(16) float   g_logits[(size_t)Mn*Vn];
__device__ __align__(16) __half  g_Wih_hi[(size_t)Ln*H3n*Hn];
__device__ __align__(16) __half  g_Wih_lo[(size_t)Ln*H3n*Hn]; // scaled x512 (unused in R15 input GEMM)
__device__ __align__(16) __half  g_Whh_hi[(size_t)Ln*H3n*Hn];
__device__ __align__(16) __half  g_Whh_lo[(size_t)Ln*H3n*Hn]; // scaled x512
__device__ __align__(16) __half  g_Wout_hi[(size_t)Vn*Hn];
__device__ __align__(16) __half  g_Wout_lo[(size_t)Vn*Hn];    // scaled x512
__device__ __align__(16) __half  g_h0h[(size_t)Ln*Bn*Hn];
__device__ __align__(16) __half  g_h0l[(size_t)Ln*Bn*Hn];
__device__ unsigned g_barrier;

// ---------------- helpers ----------------
#define MMA_F16(d, a, b)                                                      \
  asm volatile("mma.sync.aligned.m16n8k16.row.col.f32.f16.f16.f32 "           \
               "{%0,%1,%2,%3},{%4,%5,%6,%7},{%8,%9},{%0,%1,%2,%3};"           \
               : "+f"(d[0]), "+f"(d[1]), "+f"(d[2]), "+f"(d[3])               \
               : "r"(a[0]), "r"(a[1]), "r"(a[2]), "r"(a[3]),                  \
                 "r"(b[0]), "r"(b[1]))

#define LDSM_X4(r0, r1, r2, r3, a)                                            \
  asm volatile("ldmatrix.sync.aligned.m8n8.x4.shared.b16 {%0,%1,%2,%3}, [%4];"\
               : "=r"(r0), "=r"(r1), "=r"(r2), "=r"(r3) : "r"(a))
#define LDSM_X2(r0, r1, a)                                                    \
  asm volatile("ldmatrix.sync.aligned.m8n8.x2.shared.b16 {%0,%1}, [%2];"      \
               : "=r"(r0), "=r"(r1) : "r"(a))

__device__ __forceinline__ unsigned lds_u32(const __half* s, int row, int ld, int col) {
    return *reinterpret_cast<const unsigned*>(s + row * ld + col);
}

__device__ __forceinline__ unsigned smem_u32(const void* p) {
    return (unsigned)__cvta_generic_to_shared(p);
}

__device__ __forceinline__ void cpa16(void* dst, const void* src) {
    unsigned d = (unsigned)__cvta_generic_to_shared(dst);
    asm volatile("cp.async.cg.shared.global [%0], [%1], 16;\n" :: "r"(d), "l"(src));
}
#define CPA_COMMIT() asm volatile("cp.async.commit_group;\n" ::: "memory")
#define CPA_WAIT(n)  asm volatile("cp.async.wait_group %0;\n" :: "n"(n) : "memory")

// ---------------- elementwise kernels ----------------
__global__ void embed_split(const int* __restrict__ X, const float* __restrict__ emb,
                            __half* __restrict__ xhi) {
    long long i = (long long)blockIdx.x * blockDim.x + threadIdx.x;
    if (i < (long long)Mn * En) {
        int m = (int)(i >> 10);
        int e = (int)(i & 1023);
        int tok = X[m];
        xhi[i] = __float2half(emb[(size_t)tok * En + e]);
    }
}

// One kernel: split all weights + h0; reset barrier. lo pre-scaled x512.
#define SA_T1 ((long long)Ln*H3n*Hn)                 // 6,291,456
#define SA_T2 (SA_T1 + (long long)Ln*H3n*Hn)         // 12,582,912
#define SA_T3 (SA_T2 + (long long)Vn*Hn)             // 12,845,056
#define SA_T4 (SA_T3 + (long long)Ln*Bn*Hn)          // 12,976,128
__global__ void split_all(const float* __restrict__ W_ih, const float* __restrict__ W_hh,
                          const float* __restrict__ W_out, const float* __restrict__ h0,
                          __half* __restrict__ wihH, __half* __restrict__ wihL,
                          __half* __restrict__ whhH, __half* __restrict__ whhL,
                          __half* __restrict__ woH,  __half* __restrict__ woL,
                          __half* __restrict__ h0h,  __half* __restrict__ h0l) {
    long long i = (long long)blockIdx.x * blockDim.x + threadIdx.x;
    if (i == 0) g_barrier = 0u;
    if (i >= SA_T4) return;
    float v;
    __half *ph, *pl;
    if (i < SA_T1)      { long long j = i;          v = W_ih[j];  ph = wihH + j; pl = wihL + j; }
    else if (i < SA_T2) { long long j = i - SA_T1;  v = W_hh[j];  ph = whhH + j; pl = whhL + j; }
    else if (i < SA_T3) { long long j = i - SA_T2;  v = W_out[j]; ph = woH + j;  pl = woL + j; }
    else                { long long j = i - SA_T3;  v = h0[j];    ph = h0h + j;  pl = h0l + j; }
    __half h = __float2half(v);
    *ph = h;
    *pl = __float2half((v - __half2float(h)) * LOSCALE);
}

__global__ void copy_out(const float* __restrict__ logits, float* __restrict__ out) {
    int i = blockIdx.x * blockDim.x + threadIdx.x;
    int b   = i / (511 * Vn);
    int rem = i - b * (511 * Vn);
    int t   = rem >> 8;
    int v   = rem & 255;
    out[i] = logits[(((size_t)b * Tn + t) << 8) + v];
}

// ---------------- plain fp16 GEMM (1-term): C = A*B^T + bias ----------------
// BM=128, BN=64, BK=32, 256 threads (8 warps 4m x 2n). 3-stage cp.async.
#define GLD 40
#define G1_STAGE 7680   // elems: A[0,5120) B[5120,7680)
#define SMEM_GEMM1 (3 * G1_STAGE * 2)

__device__ __forceinline__ void gemm1_load_stage(
    const __half* A, const __half* B,
    __half* base, int tid, int bm, int bn, int k0, int Kdim) {
#pragma unroll
    for (int p = 0; p < 2; p++) {                    // A: 512 ops
        int i = tid + p * 256;
        int row = i >> 2, ch = i & 3;
        cpa16(base + row * GLD + ch * 8,
              A + (size_t)(bm + row) * Kdim + k0 + ch * 8);
    }
    {                                                // B: 256 ops
        int row = tid >> 2, ch = tid & 3;
        cpa16(base + 5120 + row * GLD + ch * 8,
              B + (size_t)(bn + row) * Kdim + k0 + ch * 8);
    }
    CPA_COMMIT();
}

__global__ __launch_bounds__(256) void gemm_plain(
    const __half* __restrict__ A, const __half* __restrict__ B,
    const float* __restrict__ bias, float* __restrict__ C,
    int Ndim, int Kdim) {
    extern __shared__ __half dsm[];

    int tid = threadIdx.x;
    int warp = tid >> 5, lane = tid & 31;
    int g = lane >> 2, tg = lane & 3;
    int wm = warp >> 1, wn = warp & 1;
    int bm = blockIdx.y * 128, bn = blockIdx.x * 64;

    float acc[2][4][4];
#pragma unroll
    for (int a = 0; a < 2; a++)
#pragma unroll
        for (int b = 0; b < 4; b++)
#pragma unroll
            for (int c = 0; c < 4; c++) acc[a][b][c] = 0.f;

    int NCk = Kdim >> 5;
    gemm1_load_stage(A, B, dsm,            tid, bm, bn, 0,  Kdim);
    gemm1_load_stage(A, B, dsm + G1_STAGE, tid, bm, bn, 32, Kdim);

    for (int c = 0; c < NCk; c++) {
        CPA_WAIT(1);
        __syncthreads();
        if (c + 2 < NCk)
            gemm1_load_stage(A, B, dsm + ((c + 2) % 3) * G1_STAGE,
                             tid, bm, bn, (c + 2) * 32, Kdim);

        const __half* sA = dsm + (c % 3) * G1_STAGE;
        const __half* sB = sA + 5120;

#pragma unroll
        for (int ks = 0; ks < 2; ks++) {
            int kk = ks * 16;
            unsigned ah[2][4], bh[4][2];
#pragma unroll
            for (int mt = 0; mt < 2; mt++) {
                int r = wm * 32 + mt * 16 + g;
                ah[mt][0] = lds_u32(sA, r,     GLD, kk + tg * 2);
                ah[mt][1] = lds_u32(sA, r + 8, GLD, kk + tg * 2);
                ah[mt][2] = lds_u32(sA, r,     GLD, kk + 8 + tg * 2);
                ah[mt][3] = lds_u32(sA, r + 8, GLD, kk + 8 + tg * 2);
            }
#pragma unroll
            for (int nt = 0; nt < 4; nt++) {
                int r = wn * 32 + nt * 8 + g;
                bh[nt][0] = lds_u32(sB, r, GLD, kk + tg * 2);
                bh[nt][1] = lds_u32(sB, r, GLD, kk + 8 + tg * 2);
            }
#pragma unroll
            for (int mt = 0; mt < 2; mt++)
#pragma unroll
                for (int nt = 0; nt < 4; nt++)
                    MMA_F16(acc[mt][nt], ah[mt], bh[nt]);
        }
    }

#pragma unroll
    for (int mt = 0; mt < 2; mt++)
#pragma unroll
        for (int nt = 0; nt < 4; nt++) {
            int r = bm + wm * 32 + mt * 16 + g;
            int cn = bn + wn * 32 + nt * 8 + tg * 2;
            float b0 = bias[cn], b1 = bias[cn + 1];
            *reinterpret_cast<float2*>(&C[(size_t)r * Ndim + cn]) =
                make_float2(acc[mt][nt][0] + b0, acc[mt][nt][1] + b1);
            *reinterpret_cast<float2*>(&C[(size_t)(r + 8) * Ndim + cn]) =
                make_float2(acc[mt][nt][2] + b0, acc[mt][nt][3] + b1);
        }
}

// ---------------- split GEMM (3-term, output GEMM only) ----------------
// C = A_hi*(Bh + Bl/512) + A_lo/512 * Bh + bias
#define G_STAGE 15360   // Ah[0,5120) Al[5120,10240) Bh[10240,12800) Bl[12800,15360)
#define SMEM_GEMM (3 * G_STAGE * 2)

__device__ __forceinline__ void gemm_load_stage(
    const __half* Ahi, const __half* Alo,
    const __half* Bhi, const __half* Blo,
    __half* base, int tid, int bm, int bn, int k0, int Kdim) {
#pragma unroll
    for (int p = 0; p < 2; p++) {
        int i = tid + p * 256;
        int row = i >> 2, ch = i & 3;
        cpa16(base + row * GLD + ch * 8,
              Ahi + (size_t)(bm + row) * Kdim + k0 + ch * 8);
        cpa16(base + 5120 + row * GLD + ch * 8,
              Alo + (size_t)(bm + row) * Kdim + k0 + ch * 8);
    }
    {
        int row = tid >> 2, ch = tid & 3;
        cpa16(base + 10240 + row * GLD + ch * 8,
              Bhi + (size_t)(bn + row) * Kdim + k0 + ch * 8);
        cpa16(base + 12800 + row * GLD + ch * 8,
              Blo + (size_t)(bn + row) * Kdim + k0 + ch * 8);
    }
    CPA_COMMIT();
}

__global__ __launch_bounds__(256) void gemm_split3(
    const __half* __restrict__ Ahi, const __half* __restrict__ Alo,
    const __half* __restrict__ Bhi, const __half* __restrict__ Blo,
    const float* __restrict__ bias, float* __restrict__ C,
    int Ndim, int Kdim) {
    extern __shared__ __half dsm[];

    int tid = threadIdx.x;
    int warp = tid >> 5, lane = tid & 31;
    int g = lane >> 2, tg = lane & 3;
    int wm = warp >> 1, wn = warp & 1;
    int bm = blockIdx.y * 128, bn = blockIdx.x * 64;

    float acc[2][4][4];
#pragma unroll
    for (int a = 0; a < 2; a++)
#pragma unroll
        for (int b = 0; b < 4; b++)
#pragma unroll
            for (int c = 0; c < 4; c++) acc[a][b][c] = 0.f;

    int NCk = Kdim >> 5;
    gemm_load_stage(Ahi, Alo, Bhi, Blo, dsm,           tid, bm, bn, 0,  Kdim);
    gemm_load_stage(Ahi, Alo, Bhi, Blo, dsm + G_STAGE, tid, bm, bn, 32, Kdim);

    for (int c = 0; c < NCk; c++) {
        CPA_WAIT(1);
        __syncthreads();
        if (c + 2 < NCk)
            gemm_load_stage(Ahi, Alo, Bhi, Blo, dsm + ((c + 2) % 3) * G_STAGE,
                            tid, bm, bn, (c + 2) * 32, Kdim);

        const __half* sAh = dsm + (c % 3) * G_STAGE;
        const __half* sAl = sAh + 5120;
        const __half* sBh = sAh + 10240;
        const __half* sBl = sAh + 12800;

#pragma unroll
        for (int ks = 0; ks < 2; ks++) {
            int kk = ks * 16;
            unsigned ah[2][4], al[2][4], bh[4][2], bl[4][2];
#pragma unroll
            for (int mt = 0; mt < 2; mt++) {
                int r = wm * 32 + mt * 16 + g;
                ah[mt][0] = lds_u32(sAh, r,     GLD, kk + tg * 2);
                ah[mt][1] = lds_u32(sAh, r + 8, GLD, kk + tg * 2);
                ah[mt][2] = lds_u32(sAh, r,     GLD, kk + 8 + tg * 2);
                ah[mt][3] = lds_u32(sAh, r + 8, GLD, kk + 8 + tg * 2);
                al[mt][0] = lds_u32(sAl, r,     GLD, kk + tg * 2);
                al[mt][1] = lds_u32(sAl, r + 8, GLD, kk + tg * 2);
                al[mt][2] = lds_u32(sAl, r,     GLD, kk + 8 + tg * 2);
                al[mt][3] = lds_u32(sAl, r + 8, GLD, kk + 8 + tg * 2);
            }
#pragma unroll
            for (int nt = 0; nt < 4; nt++) {
                int r = wn * 32 + nt * 8 + g;
                bh[nt][0] = lds_u32(sBh, r, GLD, kk + tg * 2);
                bh[nt][1] = lds_u32(sBh, r, GLD, kk + 8 + tg * 2);
                bl[nt][0] = lds_u32(sBl, r, GLD, kk + tg * 2);
                bl[nt][1] = lds_u32(sBl, r, GLD, kk + 8 + tg * 2);
            }
#pragma unroll
            for (int mt = 0; mt < 2; mt++)
#pragma unroll
                for (int nt = 0; nt < 4; nt++) {
                    float tmp[4] = {0.f, 0.f, 0.f, 0.f};
                    MMA_F16(tmp, ah[mt], bl[nt]);
                    MMA_F16(tmp, al[mt], bh[nt]);
                    MMA_F16(acc[mt][nt], ah[mt], bh[nt]);
#pragma unroll
                    for (int q = 0; q < 4; q++) acc[mt][nt][q] += tmp[q] * LOINV;
                }
        }
    }

#pragma unroll
    for (int mt = 0; mt < 2; mt++)
#pragma unroll
        for (int nt = 0; nt < 4; nt++) {
            int r = bm + wm * 32 + mt * 16 + g;
            int cn = bn + wn * 32 + nt * 8 + tg * 2;
            float b0 = bias[cn], b1 = bias[cn + 1];
            *reinterpret_cast<float2*>(&C[(size_t)r * Ndim + cn]) =
                make_float2(acc[mt][nt][0] + b0, acc[mt][nt][1] + b1);
            *reinterpret_cast<float2*>(&C[(size_t)(r + 8) * Ndim + cn]) =
                make_float2(acc[mt][nt][2] + b0, acc[mt][nt][3] + b1);
        }
}

// ---------------- persistent GRU layer kernel (2-term fp16; exact R14) ----------------
#define WLD 1032
#define HLD 40
#define HSTG 4
#define HWRP (HSTG * 16 * HLD)                       // 2560 fp16 per warp staging
#define SMEM_GRU (24*WLD*2*2 + 8*HWRP*2 + 64*24*4 + 24*4 + 4*32*12*4)

__device__ __forceinline__ void gru_load_h(
    const __half* hin, size_t rstride,
    __half* sHw, int rg, int kh, int lane, int chunk, int stage) {
#pragma unroll
    for (int p = 0; p < 2; p++) {
        int i = lane + p * 32;
        int row = i >> 2, ch = i & 3;
        cpa16(sHw + stage * 16 * HLD + row * HLD + ch * 8,
              hin + (size_t)(rg * 16 + row) * rstride + kh * 512 + chunk * 32 + ch * 8);
    }
    CPA_COMMIT();
}

__global__ void __launch_bounds__(256, 1) gru_layer(
    const __half* __restrict__ Whh_hi, const __half* __restrict__ Whh_lo,
    const float* __restrict__ bhh, const float* __restrict__ gx,
    const __half* __restrict__ h0h,
    const float* __restrict__ h0f,
    __half* __restrict__ y_hi, __half* __restrict__ y_lo,
    int bar_base) {
    extern __shared__ char smem[];
    __half* sWh = (__half*)smem;                     // 24 x 1032
    __half* sWl = sWh + 24 * WLD;
    __half* sH  = sWl + 24 * WLD;                    // [8 warps][HSTG][16*40]
    float*  sGx = (float*)(sH + 8 * HWRP);           // [64][24]
    float*  sB  = sGx + 64 * 24;                     // 24
    float*  sRed= sB + 24;                           // [4 rg][32 lane][12]

    const int tid  = threadIdx.x;
    const int warp = tid >> 5;
    const int lane = tid & 31;
    const int g    = lane >> 2;
    const int tg   = lane & 3;
    const int rg   = warp >> 1;
    const int kh   = warp & 1;
    const int c0   = blockIdx.x * 8;

    for (int i = tid; i < 24 * 128; i += 256) {
        int r = i >> 7, blk = i & 127;
        int w = (r >> 3) * 1024 + c0 + (r & 7);
        *reinterpret_cast<uint4*>(sWh + r * WLD + blk * 8) =
            *(reinterpret_cast<const uint4*>(Whh_hi + (size_t)w * Hn) + blk);
        *reinterpret_cast<uint4*>(sWl + r * WLD + blk * 8) =
            *(reinterpret_cast<const uint4*>(Whh_lo + (size_t)w * Hn) + blk);
    }
    if (tid < 24) sB[tid] = bhh[(tid >> 3) * 1024 + c0 + (tid & 7)];

    float hreg[4];
#pragma unroll
    for (int half = 0; half < 2; half++)
#pragma unroll
        for (int c = 0; c < 2; c++)
            hreg[half * 2 + c] = h0f[(rg * 16 + g + half * 8) * Hn + c0 + tg * 2 + c];

    __syncthreads();

    __half* sHw = sH + warp * HWRP;
    float*  sGw = sGx + rg * 16 * 24;

    const unsigned sHw_u = smem_u32(sHw);
    const unsigned sWh_u = smem_u32(sWh);
    const unsigned sWl_u = smem_u32(sWl);
    const unsigned aOff  = (unsigned)(((lane & 15) * HLD + (lane >> 4) * 8) * 2);
    const unsigned b4Off = (unsigned)((((lane & 7) + ((lane >> 4) << 3)) * WLD
                                      + ((lane >> 3) & 1) * 8) * 2);
    const unsigned b2Off = (unsigned)(((16 + (lane & 7)) * WLD
                                      + ((lane >> 3) & 1) * 8) * 2);

    for (int t = 0; t < Tn; t++) {
        const __half* hin;
        size_t rstride;
        if (t == 0) { hin = h0h; rstride = Hn; }
        else        { hin = y_hi + (size_t)(t - 1) * Hn; rstride = (size_t)Tn * Hn; }

        if (kh == 0) {
#pragma unroll
            for (int p = 0; p < 3; p++) {
                int i = lane + p * 32;
                int row = i / 6, seg = i % 6;
                int gate = seg >> 1, part = seg & 1;
                cpa16(sGw + row * 24 + gate * 8 + part * 4,
                      gx + ((size_t)(rg * 16 + row) * Tn + t) * H3n
                         + gate * 1024 + c0 + part * 4);
            }
        }
        CPA_COMMIT();

#pragma unroll
        for (int s = 0; s < HSTG - 1; s++)
            gru_load_h(hin, rstride, sHw, rg, kh, lane, s, s);

        float acc[3][4], accLo[3][4];
#pragma unroll
        for (int a = 0; a < 3; a++)
#pragma unroll
            for (int b = 0; b < 4; b++) { acc[a][b] = 0.f; accLo[a][b] = 0.f; }

        for (int kc = 0; kc < 16; kc++) {
            if (kc + 3 < 16)
                gru_load_h(hin, rstride, sHw, rg, kh, lane, kc + 3, (kc + 3) % HSTG);

            if      (kc < 13)  CPA_WAIT(3);
            else if (kc == 13) CPA_WAIT(2);
            else if (kc == 14) CPA_WAIT(1);
            else               CPA_WAIT(0);
            __syncwarp();

            const unsigned stH = sHw_u + (unsigned)((kc % HSTG) * 16 * HLD * 2);
#pragma unroll
            for (int ks = 0; ks < 2; ks++) {
                const unsigned kb = (unsigned)(ks * 16 * 2);
                const unsigned kcol2 = (unsigned)((kh * 512 + kc * 32 + ks * 16) * 2);
                unsigned ah[4], bh01[4], bl01[4], bh2[2], bl2[2];
                LDSM_X4(ah[0], ah[1], ah[2], ah[3], stH + aOff + kb);
                LDSM_X4(bh01[0], bh01[1], bh01[2], bh01[3], sWh_u + b4Off + kcol2);
                LDSM_X2(bh2[0], bh2[1], sWh_u + b2Off + kcol2);
                LDSM_X4(bl01[0], bl01[1], bl01[2], bl01[3], sWl_u + b4Off + kcol2);
                LDSM_X2(bl2[0], bl2[1], sWl_u + b2Off + kcol2);
                unsigned* bH[3] = {bh01, bh01 + 2, bh2};
                unsigned* bL[3] = {bl01, bl01 + 2, bl2};
#pragma unroll
                for (int nt = 0; nt < 3; nt++) {
                    MMA_F16(acc[nt], ah, bH[nt]);
                    MMA_F16(accLo[nt], ah, bL[nt]);
                }
            }
            __syncwarp();
        }

#pragma unroll
        for (int nt = 0; nt < 3; nt++)
#pragma unroll
            for (int i = 0; i < 4; i++) acc[nt][i] += accLo[nt][i] * LOINV;

        if (kh == 1) {
            float* r = sRed + (rg * 32 + lane) * 12;
#pragma unroll
            for (int nt = 0; nt < 3; nt++)
#pragma unroll
                for (int i = 0; i < 4; i++) r[nt * 4 + i] = acc[nt][i];
        }
        __syncthreads();

        if (kh == 0) {
            const float* r = sRed + (rg * 32 + lane) * 12;
#pragma unroll
            for (int nt = 0; nt < 3; nt++)
#pragma unroll
                for (int i = 0; i < 4; i++) acc[nt][i] += r[nt * 4 + i];

#pragma unroll
            for (int half = 0; half < 2; half++) {
                __half hh2[2], hl2[2];
#pragma unroll
                for (int c = 0; c < 2; c++) {
                    int rl = g + half * 8;
                    int jl = tg * 2 + c;
                    int ai = half * 2 + c;
                    float gr = acc[0][ai] + sB[jl];
                    float gz = acc[1][ai] + sB[8 + jl];
                    float gn = acc[2][ai] + sB[16 + jl];
                    float rr = 1.f / (1.f + __expf(-(sGw[rl * 24 + jl] + gr)));
                    float zz = 1.f / (1.f + __expf(-(sGw[rl * 24 + 8 + jl] + gz)));
                    float nn = tanhf(sGw[rl * 24 + 16 + jl] + rr * gn);
                    float hv = (1.f - zz) * nn + zz * hreg[ai];
                    hreg[ai] = hv;
                    __half h_ = __float2half(hv);
                    hh2[c] = h_;
                    hl2[c] = __float2half((hv - __half2float(h_)) * LOSCALE);
                }
                int b = rg * 16 + g + half * 8;
                size_t off = ((size_t)b * Tn + t) * Hn + c0 + tg * 2;
                *reinterpret_cast<__half2*>(y_hi + off) = *reinterpret_cast<__half2*>(hh2);
                *reinterpret_cast<__half2*>(y_lo + off) = *reinterpret_cast<__half2*>(hl2);
            }
        }

        if (t < Tn - 1) {
            __syncthreads();
            if (tid == 0) {
                __threadfence();
                atomicAdd(&g_barrier, 1u);
                unsigned tgt = (unsigned)(bar_base + (t + 1) * NCTA);
                while (*(volatile unsigned*)&g_barrier < tgt) { }
                __threadfence();
            }
            __syncthreads();
        }
    }
}

// ---------------- host orchestration ----------------
extern "C" void kernel_launch(void* const* d_in, const int* in_sizes, int n_in,
                              void* d_out, int out_size) {
    (void)in_sizes; (void)n_in; (void)out_size;
    const int*   X     = (const int*)d_in[0];
    const float* h0    = (const float*)d_in[1];
    const float* emb   = (const float*)d_in[2];
    const float* W_ih  = (const float*)d_in[3];
    const float* W_hh  = (const float*)d_in[4];
    const float* b_ih  = (const float*)d_in[5];
    const float* b_hh  = (const float*)d_in[6];
    const float* W_out = (const float*)d_in[7];
    const float* b_out = (const float*)d_in[8];
    float* out = (float*)d_out;

    float *gx, *logits;
    __half *xhi, *y1hi, *y1lo, *y2hi, *y2lo;
    __half *wihH, *wihL, *whhH, *whhL, *woH, *woL;
    __half *h0h, *h0lp;
    cudaGetSymbolAddress((void**)&gx, g_gx);
    cudaGetSymbolAddress((void**)&logits, g_logits);
    cudaGetSymbolAddress((void**)&xhi, g_x_hi);
    cudaGetSymbolAddress((void**)&y1hi, g_y1_hi);
    cudaGetSymbolAddress((void**)&y1lo, g_y1_lo);
    cudaGetSymbolAddress((void**)&y2hi, g_y2_hi);
    cudaGetSymbolAddress((void**)&y2lo, g_y2_lo);
    cudaGetSymbolAddress((void**)&wihH, g_Wih_hi);
    cudaGetSymbolAddress((void**)&wihL, g_Wih_lo);
    cudaGetSymbolAddress((void**)&whhH, g_Whh_hi);
    cudaGetSymbolAddress((void**)&whhL, g_Whh_lo);
    cudaGetSymbolAddress((void**)&woH, g_Wout_hi);
    cudaGetSymbolAddress((void**)&woL, g_Wout_lo);
    cudaGetSymbolAddress((void**)&h0h, g_h0h);
    cudaGetSymbolAddress((void**)&h0lp, g_h0l);
    const size_t HB = (size_t)Bn * Hn;

    cudaFuncSetAttribute(gru_layer, cudaFuncAttributeMaxDynamicSharedMemorySize, SMEM_GRU);
    cudaFuncSetAttribute(gemm_plain, cudaFuncAttributeMaxDynamicSharedMemorySize, SMEM_GEMM1);
    cudaFuncSetAttribute(gemm_split3, cudaFuncAttributeMaxDynamicSharedMemorySize, SMEM_GEMM);

    dim3 gg(H3n / 64, Mn / 128);

    // Launch order: embed(1), split_all(2), gemmL0(3), gruL0(4) <- ncu slot 4
    embed_split<<<(int)(((long long)Mn * En) / 256), 256>>>(X, emb, xhi);
    split_all<<<(int)((SA_T4 + 255) / 256), 256>>>(W_ih, W_hh, W_out, h0,
                                                   wihH, wihL, whhH, whhL,
                                                   woH, woL, h0h, h0lp);

    for (int l = 0; l < Ln; l++) {
        const __half* aH = (l == 0) ? xhi : y1hi;
        __half* yH = (l == 0) ? y1hi : y2hi;
        __half* yL = (l == 0) ? y1lo : y2lo;
        size_t wOff = (size_t)l * H3n * Hn;

        // input GEMM: 1-term plain fp16
        gemm_plain<<<gg, 256, SMEM_GEMM1>>>(aH, wihH + wOff,
                                            b_ih + (size_t)l * H3n, gx, H3n, Hn);
        gru_layer<<<NCTA, 256, SMEM_GRU>>>(whhH + wOff, whhL + wOff,
                                           b_hh + (size_t)l * H3n, gx,
                                           h0h + l * HB,
                                           h0 + (size_t)l * HB, yH, yL,
                                           l * (Tn - 1) * NCTA);
    }

    // output GEMM: 3-term (y split + W split; both lo x512)
    dim3 gl(Vn / 64, Mn / 128);
    gemm_split3<<<gl, 256, SMEM_GEMM>>>(y2hi, y2lo, woH, woL, b_out, logits, Vn, Hn);

    copy_out<<<(Bn * 511 * Vn) / 256, 256>>>(logits, out);
}